// round 1
// baseline (speedup 1.0000x reference)
#include <cuda_runtime.h>
#include <cstdint>
#include <math.h>

// ---------------- problem constants ----------------
#define KDIM 100352          // 2048*49
#define MDIM 256             // b*t
#define NDIM 1024            // D = H*d
#define NF   2048
#define TT   32
#define SQRT_NF 45.254833995939045f
#define INV_SQRT_BN 0.9999950000374997f   // 1/sqrt(1+1e-5)

// ---------------- GEMM tiling ----------------
#define BM 128
#define BN 128
#define BK 32
#define LROW 36              // BK + 4 pad (floats) -> conflict-free lds
#define SPLITK 9
#define KTILES 3136          // KDIM/BK
#define CHUNK  349           // ceil(KTILES/SPLITK); last chunk = 344

// ---------------- scratch (allocation-free: device globals) ----------------
__device__ float g_A[(size_t)MDIM * KDIM];            // scaled+biased A (102.8 MB)
__device__ float g_part[(size_t)SPLITK * MDIM * NDIM]; // split-K partials
__device__ float g_xqn[MDIM * NDIM];                   // layernormed xq
__device__ float g_off[TT * NF];                       // beta*sqrtNF + pe[t][c]
__device__ float g_sc[NF];                             // per-channel scale

// ================= prep: scales + positional encoding =================
__global__ void prep_scales(const float* __restrict__ gamma,
                            const float* __restrict__ beta) {
    int idx = blockIdx.x * 256 + threadIdx.x;      // 65536 = 32*2048
    int t = idx >> 11;
    int c = idx & (NF - 1);
    // pe[t,c] = sin(t * 10000^(-2c/NF)) if c even else cos(...)
    float w = __expf(-(2.0f * (float)c / (float)NF) * 9.210340371976184f); // ln(10000)
    float ang = (float)t * w;
    float pe = (c & 1) ? cosf(ang) : sinf(ang);
    g_off[idx] = beta[c] * SQRT_NF + pe;
    if (idx < NF) g_sc[idx] = gamma[idx] * SQRT_NF * INV_SQRT_BN;
}

// ================= prep: A[n,k] = x[n,k]*sc[c] + off[t(n),c] =================
__global__ void prep_A(const float* __restrict__ x) {
    int n = blockIdx.y;
    int k = blockIdx.x * 256 + threadIdx.x;        // gridDim.x = KDIM/256 = 392
    int c = k / 49;
    size_t id = (size_t)n * KDIM + k;
    g_A[id] = x[id] * g_sc[c] + g_off[(n & 31) * NF + c];
}

// ================= 3xTF32 GEMM =================
__device__ __forceinline__ void split_tf32(float x, uint32_t& hi, uint32_t& lo) {
    uint32_t h, l;
    asm("cvt.rna.tf32.f32 %0, %1;" : "=r"(h) : "f"(x));
    float r = x - __uint_as_float(h);
    asm("cvt.rna.tf32.f32 %0, %1;" : "=r"(l) : "f"(r));
    hi = h; lo = l;
}

__device__ __forceinline__ void mma8(float* c, const uint32_t* a, const uint32_t* b) {
    asm volatile(
        "mma.sync.aligned.m16n8k8.row.col.f32.tf32.tf32.f32 "
        "{%0,%1,%2,%3},{%4,%5,%6,%7},{%8,%9},{%0,%1,%2,%3};"
        : "+f"(c[0]), "+f"(c[1]), "+f"(c[2]), "+f"(c[3])
        : "r"(a[0]), "r"(a[1]), "r"(a[2]), "r"(a[3]), "r"(b[0]), "r"(b[1]));
}

__global__ void __launch_bounds__(256) gemm_k(const float* __restrict__ Wt) {
    extern __shared__ float sm[];
    float* As = sm;                    // [2][BM*LROW]
    float* Bs = sm + 2 * BM * LROW;    // [2][BN*LROW]

    const int nt = blockIdx.x, mt = blockIdx.y, ks = blockIdx.z;
    const int k0t = ks * CHUNK;
    int nkt = KTILES - k0t; if (nkt > CHUNK) nkt = CHUNK;

    const int tid = threadIdx.x;
    const int lane = tid & 31, wid = tid >> 5;
    const int wm = wid >> 2, wn = wid & 3;     // 2x4 warp grid, 64x32 per warp
    const int g = lane >> 2, tg = lane & 3;

    const float* Ab = g_A + (size_t)(mt * BM) * KDIM;
    const float* Bb = Wt  + (size_t)(nt * BN) * KDIM;

    auto ld = [&](int buf, size_t kcol) {
#pragma unroll
        for (int i = 0; i < 4; i++) {
            int idx = tid + i * 256;          // 1024 float4 per tile
            int row = idx >> 3, c4 = (idx & 7) << 2;
            unsigned sa = (unsigned)__cvta_generic_to_shared(
                &As[buf * BM * LROW + row * LROW + c4]);
            const float* gp = Ab + (size_t)row * KDIM + kcol + c4;
            asm volatile("cp.async.cg.shared.global [%0], [%1], 16;" :: "r"(sa), "l"(gp));
            unsigned sb = (unsigned)__cvta_generic_to_shared(
                &Bs[buf * BM * LROW + row * LROW + c4]);
            const float* gq = Bb + (size_t)row * KDIM + kcol + c4;
            asm volatile("cp.async.cg.shared.global [%0], [%1], 16;" :: "r"(sb), "l"(gq));
        }
        asm volatile("cp.async.commit_group;" ::: "memory");
    };

    float acc[4][4][4];
#pragma unroll
    for (int a = 0; a < 4; a++)
#pragma unroll
        for (int b = 0; b < 4; b++)
#pragma unroll
            for (int cc = 0; cc < 4; cc++) acc[a][b][cc] = 0.f;

    size_t base = (size_t)k0t * BK;
    ld(0, base);
    for (int kt = 0; kt < nkt; kt++) {
        if (kt + 1 < nkt) {
            ld((kt + 1) & 1, base + (size_t)(kt + 1) * BK);
            asm volatile("cp.async.wait_group 1;" ::: "memory");
        } else {
            asm volatile("cp.async.wait_group 0;" ::: "memory");
        }
        __syncthreads();
        const float* Ap = As + (kt & 1) * BM * LROW;
        const float* Bp = Bs + (kt & 1) * BM * LROW;
#pragma unroll
        for (int k8 = 0; k8 < 4; k8++) {
            const int kk = k8 * 8;
            uint32_t ahi[4][4], alo[4][4], bhi[4][2], blo[4][2];
#pragma unroll
            for (int mi = 0; mi < 4; mi++) {
                int r = wm * 64 + mi * 16 + g;
                split_tf32(Ap[r * LROW + kk + tg],           ahi[mi][0], alo[mi][0]);
                split_tf32(Ap[(r + 8) * LROW + kk + tg],     ahi[mi][1], alo[mi][1]);
                split_tf32(Ap[r * LROW + kk + tg + 4],       ahi[mi][2], alo[mi][2]);
                split_tf32(Ap[(r + 8) * LROW + kk + tg + 4], ahi[mi][3], alo[mi][3]);
            }
#pragma unroll
            for (int ni = 0; ni < 4; ni++) {
                int c = wn * 32 + ni * 8 + g;
                split_tf32(Bp[c * LROW + kk + tg],     bhi[ni][0], blo[ni][0]);
                split_tf32(Bp[c * LROW + kk + tg + 4], bhi[ni][1], blo[ni][1]);
            }
#pragma unroll
            for (int mi = 0; mi < 4; mi++)
#pragma unroll
                for (int ni = 0; ni < 4; ni++) {
                    mma8(acc[mi][ni], alo[mi], bhi[ni]);
                    mma8(acc[mi][ni], ahi[mi], blo[ni]);
                    mma8(acc[mi][ni], ahi[mi], bhi[ni]);
                }
        }
        __syncthreads();
    }

    float* outp = g_part + (size_t)ks * MDIM * NDIM;
#pragma unroll
    for (int mi = 0; mi < 4; mi++) {
        int r = mt * BM + wm * 64 + mi * 16 + g;
#pragma unroll
        for (int ni = 0; ni < 4; ni++) {
            int c = nt * BN + wn * 32 + ni * 8 + 2 * tg;
            *(float2*)&outp[(size_t)r * NDIM + c] =
                make_float2(acc[mi][ni][0], acc[mi][ni][1]);
            *(float2*)&outp[(size_t)(r + 8) * NDIM + c] =
                make_float2(acc[mi][ni][2], acc[mi][ni][3]);
        }
    }
}

// ============ split-K reduce + ReLU + LayerNorm(ddof=1) over D ============
__global__ void reduce_ln() {
    int row = blockIdx.x, tid = threadIdx.x;
    float v[4], s = 0.f, ss = 0.f;
#pragma unroll
    for (int j = 0; j < 4; j++) {
        int col = tid + j * 256;
        float a = 0.f;
#pragma unroll
        for (int sk = 0; sk < SPLITK; sk++)
            a += g_part[((size_t)sk * MDIM + row) * NDIM + col];
        a = fmaxf(a, 0.f);
        v[j] = a; s += a; ss += a * a;
    }
    __shared__ float r1[8], r2[8];
#pragma unroll
    for (int o = 16; o > 0; o >>= 1) {
        s  += __shfl_xor_sync(0xffffffffu, s, o);
        ss += __shfl_xor_sync(0xffffffffu, ss, o);
    }
    if ((tid & 31) == 0) { r1[tid >> 5] = s; r2[tid >> 5] = ss; }
    __syncthreads();
    if (tid == 0) {
        float S = 0.f, SS = 0.f;
        for (int w = 0; w < 8; w++) { S += r1[w]; SS += r2[w]; }
        r1[0] = S; r2[0] = SS;
    }
    __syncthreads();
    float mean = r1[0] * (1.f / 1024.f);
    float var  = (r2[0] - 1024.f * mean * mean) * (1.f / 1023.f);
    float inv  = 1.f / (sqrtf(fmaxf(var, 0.f)) + 1e-6f);
#pragma unroll
    for (int j = 0; j < 4; j++)
        g_xqn[row * NDIM + tid + j * 256] = (v[j] - mean) * inv;
}

// ============ attention tail: 3 iterations + final normalize ============
__global__ void __launch_bounds__(1024) attn_k(
    const float* __restrict__ qlw, const float* __restrict__ qlb,
    const float* __restrict__ n1a, const float* __restrict__ n1b,
    const float* __restrict__ n2a, const float* __restrict__ n2b,
    const float* __restrict__ fw1, const float* __restrict__ fb1,
    const float* __restrict__ fw2, const float* __restrict__ fb2,
    float* __restrict__ out)
{
    const int b = blockIdx.x, tid = threadIdx.x;
    const int h = tid >> 6, d = tid & 63;     // 16 x 64
    const int h2 = tid >> 5, t2 = tid & 31;   // 16 x 32 (tid < 512)

    __shared__ float qS[1024], qhS[1024], q_S[1024], zS[1024];
    __shared__ float scS[16 * 32], hidS[16 * 32];
    __shared__ float muS[16], isdS[16], redA[32];

    qS[tid] = g_xqn[(b * 32 + 16) * NDIM + tid];   // q = xq[:, t/2, :]
    __syncthreads();

    for (int i = 0; i < 3; i++) {
        // qh = relu(q @ qlin_w[i].T + qlin_b[i])
        {
            const float4* W4 = (const float4*)(qlw + ((size_t)i * 1024 + tid) * 1024);
            float acc = qlb[i * 1024 + tid];
#pragma unroll 8
            for (int k4 = 0; k4 < 256; k4++) {
                float4 w = W4[k4];
                acc += w.x * qS[k4 * 4] + w.y * qS[k4 * 4 + 1]
                     + w.z * qS[k4 * 4 + 2] + w.w * qS[k4 * 4 + 3];
            }
            qhS[tid] = fmaxf(acc, 0.f);
        }
        __syncthreads();

        // scores + softmax: one warp per head, one lane per t
        if (tid < 512) {
            const float* khp = g_xqn + (b * 32 + t2) * NDIM + h2 * 64;
            const float* qp  = qhS + h2 * 64;
            float dot = 0.f;
#pragma unroll
            for (int dd = 0; dd < 64; dd++) dot += qp[dd] * khp[dd];
            dot *= 0.125f;   // 1/sqrt(64)
            float m = dot;
#pragma unroll
            for (int o = 16; o > 0; o >>= 1) m = fmaxf(m, __shfl_xor_sync(0xffffffffu, m, o));
            float e = __expf(dot - m);
            float sum = e;
#pragma unroll
            for (int o = 16; o > 0; o >>= 1) sum += __shfl_xor_sync(0xffffffffu, sum, o);
            scS[h2 * 32 + t2] = e / sum;
        }
        __syncthreads();

        // A = sc @ vh ; z = A + qh ; q_ = norm1(z)
        {
            float a = 0.f;
            const float* vb = g_xqn + (size_t)(b * 32) * NDIM + h * 64 + d;
#pragma unroll
            for (int tt = 0; tt < 32; tt++) a += scS[h * 32 + tt] * vb[tt * NDIM];
            float z = a + qhS[tid];
            zS[tid] = z;
            __syncthreads();
            if (tid < 16) {
                float s = 0.f, ssum = 0.f;
                for (int dd = 0; dd < 64; dd++) {
                    float v = zS[tid * 64 + dd]; s += v; ssum += v * v;
                }
                float mu = s * (1.f / 64.f);
                float var = (ssum - 64.f * mu * mu) * (1.f / 63.f);
                muS[tid] = mu;
                isdS[tid] = 1.f / (sqrtf(fmaxf(var, 0.f)) + 1e-6f);
            }
            __syncthreads();
            q_S[tid] = n1a[(i * 16 + h) * 64 + d] * (z - muS[h]) * isdS[h]
                     + n1b[(i * 16 + h) * 64 + d];
        }
        __syncthreads();

        // hid = relu(q_ @ ff_w1[i] + b1)
        if (tid < 512) {
            const float* w1 = fw1 + ((size_t)(i * 16 + h2) * 32 + t2) * 64;
            float acc = fb1[(i * 16 + h2) * 32 + t2];
#pragma unroll
            for (int dd = 0; dd < 64; dd++) acc += q_S[h2 * 64 + dd] * w1[dd];
            hidS[h2 * 32 + t2] = fmaxf(acc, 0.f);
        }
        __syncthreads();

        // ffo = hid @ ff_w2[i] + b2 ; q = norm2(q_ + ffo)
        {
            const float* w2 = fw2 + ((size_t)(i * 16 + h) * 64 + d) * 32;
            float acc = fb2[(i * 16 + h) * 64 + d];
#pragma unroll
            for (int ff = 0; ff < 32; ff++) acc += hidS[h * 32 + ff] * w2[ff];
            float z = q_S[tid] + acc;
            __syncthreads();
            zS[tid] = z;
            __syncthreads();
            if (tid < 16) {
                float s = 0.f, ssum = 0.f;
                for (int dd = 0; dd < 64; dd++) {
                    float v = zS[tid * 64 + dd]; s += v; ssum += v * v;
                }
                float mu = s * (1.f / 64.f);
                float var = (ssum - 64.f * mu * mu) * (1.f / 63.f);
                muS[tid] = mu;
                isdS[tid] = 1.f / (sqrtf(fmaxf(var, 0.f)) + 1e-6f);
            }
            __syncthreads();
            qS[tid] = n2a[(i * 16 + h) * 64 + d] * (z - muS[h]) * isdS[h]
                    + n2b[(i * 16 + h) * 64 + d];
        }
        __syncthreads();
    }

    // f = q / max(||q||, 1e-12)
    float v = qS[tid];
    float ssq = v * v;
#pragma unroll
    for (int o = 16; o > 0; o >>= 1) ssq += __shfl_xor_sync(0xffffffffu, ssq, o);
    if ((tid & 31) == 0) redA[tid >> 5] = ssq;
    __syncthreads();
    if (tid < 32) {
        float s2 = redA[tid];
#pragma unroll
        for (int o = 16; o > 0; o >>= 1) s2 += __shfl_xor_sync(0xffffffffu, s2, o);
        if (tid == 0) redA[0] = s2;
    }
    __syncthreads();
    float nrm = sqrtf(redA[0]);
    out[b * 1024 + tid] = v / fmaxf(nrm, 1e-12f);
}

// ================= launch =================
extern "C" void kernel_launch(void* const* d_in, const int* in_sizes, int n_in,
                              void* d_out, int out_size) {
    const float* x     = (const float*)d_in[0];
    const float* gamma = (const float*)d_in[1];
    const float* beta  = (const float*)d_in[2];
    const float* qpr   = (const float*)d_in[3];
    const float* qlw   = (const float*)d_in[4];
    const float* qlb   = (const float*)d_in[5];
    const float* n1a   = (const float*)d_in[6];
    const float* n1b   = (const float*)d_in[7];
    const float* n2a   = (const float*)d_in[8];
    const float* n2b   = (const float*)d_in[9];
    const float* fw1   = (const float*)d_in[10];
    const float* fb1   = (const float*)d_in[11];
    const float* fw2   = (const float*)d_in[12];
    const float* fb2   = (const float*)d_in[13];
    float* out = (float*)d_out;

    prep_scales<<<256, 256>>>(gamma, beta);
    prep_A<<<dim3(KDIM / 256, MDIM), 256>>>(x);

    const int smem = 4 * BM * LROW * (int)sizeof(float);  // 73728 B
    cudaFuncSetAttribute(gemm_k, cudaFuncAttributeMaxDynamicSharedMemorySize, smem);
    gemm_k<<<dim3(NDIM / BN, MDIM / BM, SPLITK), 256, smem>>>(qpr);

    reduce_ln<<<MDIM, 256>>>();
    attn_k<<<8, 1024>>>(qlw, qlb, n1a, n1b, n2a, n2b, fw1, fb1, fw2, fb2, out);
}

// round 3
// speedup vs baseline: 1.2359x; 1.2359x over previous
#include <cuda_runtime.h>
#include <cuda_bf16.h>
#include <cstdint>
#include <math.h>

// ---------------- problem constants ----------------
#define KDIM 100352          // 2048*49
#define MDIM 256             // b*t
#define NDIM 1024            // D = H*d
#define NF   2048
#define TT   32
#define SQRT_NF 45.254833995939045f
#define INV_SQRT_BN 0.9999950000374997f   // 1/sqrt(1+1e-5)

// ---------------- GEMM tiling ----------------
#define BM 128
#define BN 128
#define BK 32
#define NSTAGE 3
#define SPLITK 9
#define KTILES 3136          // KDIM/BK
#define CHUNK  349           // ceil(KTILES/SPLITK); last chunk = 344

// smem: per stage: A 128 rows x 128B (hi 64B | lo 64B) = 16KB, B same = 16KB
#define STAGE_B 32768
#define SMEM_TOTAL (NSTAGE * STAGE_B)   // 98304

// ---------------- scratch (allocation-free: device globals) ----------------
__device__ __nv_bfloat16 g_Ahi[(size_t)MDIM * KDIM];
__device__ __nv_bfloat16 g_Alo[(size_t)MDIM * KDIM];
__device__ __nv_bfloat16 g_Whi[(size_t)NDIM * KDIM];
__device__ __nv_bfloat16 g_Wlo[(size_t)NDIM * KDIM];
__device__ float g_part[(size_t)SPLITK * MDIM * NDIM]; // split-K partials
__device__ float g_xqn[MDIM * NDIM];                   // layernormed xq
__device__ float g_off[TT * NF];                       // beta*sqrtNF + pe[t][c]
__device__ float g_sc[NF];                             // per-channel scale

// ================= prep: scales + positional encoding =================
__global__ void prep_scales(const float* __restrict__ gamma,
                            const float* __restrict__ beta) {
    int idx = blockIdx.x * 256 + threadIdx.x;      // 65536 = 32*2048
    int t = idx >> 11;
    int c = idx & (NF - 1);
    float w = __expf(-(2.0f * (float)c / (float)NF) * 9.210340371976184f); // ln(10000)
    float ang = (float)t * w;
    float pe = (c & 1) ? cosf(ang) : sinf(ang);
    g_off[idx] = beta[c] * SQRT_NF + pe;
    if (idx < NF) g_sc[idx] = gamma[idx] * SQRT_NF * INV_SQRT_BN;
}

// ========== prep A: affine + bf16 hi/lo split ==========
__global__ void prep_A(const float* __restrict__ x) {
    int n = blockIdx.y;
    int k = (blockIdx.x * 256 + threadIdx.x) * 2;   // gridDim.x = KDIM/512 = 196
    size_t id = (size_t)n * KDIM + k;
    float2 xv = *(const float2*)(x + id);
    int c0 = k / 49, c1 = (k + 1) / 49;
    int to = (n & 31) * NF;
    float a0 = xv.x * g_sc[c0] + g_off[to + c0];
    float a1 = xv.y * g_sc[c1] + g_off[to + c1];
    __nv_bfloat16 h0 = __float2bfloat16(a0);
    __nv_bfloat16 h1 = __float2bfloat16(a1);
    __nv_bfloat162 hv; hv.x = h0; hv.y = h1;
    __nv_bfloat162 lv;
    lv.x = __float2bfloat16(a0 - __bfloat162float(h0));
    lv.y = __float2bfloat16(a1 - __bfloat162float(h1));
    *(__nv_bfloat162*)(g_Ahi + id) = hv;
    *(__nv_bfloat162*)(g_Alo + id) = lv;
}

// ========== prep W: bf16 hi/lo split ==========
__global__ void prep_W(const float* __restrict__ w) {
    size_t id = ((size_t)blockIdx.x * 256 + threadIdx.x) * 2;  // grid = 200704
    float2 wv = *(const float2*)(w + id);
    __nv_bfloat16 h0 = __float2bfloat16(wv.x);
    __nv_bfloat16 h1 = __float2bfloat16(wv.y);
    __nv_bfloat162 hv; hv.x = h0; hv.y = h1;
    __nv_bfloat162 lv;
    lv.x = __float2bfloat16(wv.x - __bfloat162float(h0));
    lv.y = __float2bfloat16(wv.y - __bfloat162float(h1));
    *(__nv_bfloat162*)(g_Whi + id) = hv;
    *(__nv_bfloat162*)(g_Wlo + id) = lv;
}

// ================= bf16 3-product GEMM (mma.sync m16n8k16) =================
__device__ __forceinline__ void mma16(float* c, const uint32_t* a, const uint32_t* b) {
    asm volatile(
        "mma.sync.aligned.m16n8k16.row.col.f32.bf16.bf16.f32 "
        "{%0,%1,%2,%3},{%4,%5,%6,%7},{%8,%9},{%0,%1,%2,%3};"
        : "+f"(c[0]), "+f"(c[1]), "+f"(c[2]), "+f"(c[3])
        : "r"(a[0]), "r"(a[1]), "r"(a[2]), "r"(a[3]), "r"(b[0]), "r"(b[1]));
}
__device__ __forceinline__ uint32_t lds32(uint32_t a) {
    uint32_t v;
    asm volatile("ld.shared.b32 %0, [%1];" : "=r"(v) : "r"(a));
    return v;
}

__global__ void __launch_bounds__(256) gemm_k() {
    extern __shared__ char smem[];
    const uint32_t sbase = (uint32_t)__cvta_generic_to_shared(smem);
    const int tid = threadIdx.x;
    const int lane = tid & 31, wid = tid >> 5;
    const int g = lane >> 2, tg = lane & 3;
    const int wm = wid >> 2, wn = wid & 3;          // 2x4 warps, tile 64x32
    const int nt = blockIdx.x, mt = blockIdx.y, ks = blockIdx.z;
    const int k0t = ks * CHUNK;
    int nkt = KTILES - k0t; if (nkt > CHUNK) nkt = CHUNK;
    const int k0 = k0t * BK;

    // ---- cp.async geometry: 1024 chunks of 16B each for A and B per stage ----
    // chunk c: row = c>>3, part = c&7; part<4 -> hi bytes [part*16), else lo
    const __nv_bfloat16* pA[4]; const __nv_bfloat16* pB[4];
    uint32_t dA[4], dB[4];
#pragma unroll
    for (int j = 0; j < 4; j++) {
        int c = tid + j * 256;
        int row = c >> 3, part = c & 7;
        int sub = (part < 4) ? part * 16 : 64 + (part & 3) * 16;
        uint32_t phys = (uint32_t)row * 128u + (uint32_t)(sub ^ ((row & 7) << 4));
        dA[j] = phys;                 // A region at stage base + 0
        dB[j] = 16384u + phys;        // B region at stage base + 16KB
        const __nv_bfloat16* ah = (part < 4) ? g_Ahi : g_Alo;
        const __nv_bfloat16* wh = (part < 4) ? g_Whi : g_Wlo;
        pA[j] = ah + (size_t)(mt * BM + row) * KDIM + k0 + (part & 3) * 8;
        pB[j] = wh + (size_t)(nt * BN + row) * KDIM + k0 + (part & 3) * 8;
    }

    auto load = [&](int s, int kt) {
        uint32_t sb = sbase + (uint32_t)s * STAGE_B;
        size_t koff = (size_t)kt * BK;
#pragma unroll
        for (int j = 0; j < 4; j++) {
            asm volatile("cp.async.cg.shared.global [%0], [%1], 16;"
                         :: "r"(sb + dA[j]), "l"(pA[j] + koff));
            asm volatile("cp.async.cg.shared.global [%0], [%1], 16;"
                         :: "r"(sb + dB[j]), "l"(pB[j] + koff));
        }
        asm volatile("cp.async.commit_group;" ::: "memory");
    };

    // ---- fragment address bases (swizzle reduces to (jj^g) on chunk bits) ----
    // element sub-byte = jj*16 + tg*4, jj in 0..7 covers {hi,lo} x {k16 lo/hi} x {2tg vs 2tg+8}
    uint32_t col[8];
#pragma unroll
    for (int jj = 0; jj < 8; jj++) col[jj] = (uint32_t)(((jj ^ g) << 4) + tg * 4);
    uint32_t rowA[4][2], rowB[4];
#pragma unroll
    for (int mi = 0; mi < 4; mi++) {
        rowA[mi][0] = (uint32_t)(wm * 64 + mi * 16 + g) * 128u;
        rowA[mi][1] = rowA[mi][0] + 8u * 128u;
    }
#pragma unroll
    for (int ni = 0; ni < 4; ni++) rowB[ni] = (uint32_t)(wn * 32 + ni * 8 + g) * 128u + 16384u;

    float acc[4][4][4];
#pragma unroll
    for (int a = 0; a < 4; a++)
#pragma unroll
        for (int b = 0; b < 4; b++)
#pragma unroll
            for (int cc = 0; cc < 4; cc++) acc[a][b][cc] = 0.f;

    // ---- prologue ----
    load(0, 0);
    load(1, 1);

    for (int kt = 0; kt < nkt; kt++) {
        if (kt + 1 < nkt) { asm volatile("cp.async.wait_group 1;" ::: "memory"); }
        else              { asm volatile("cp.async.wait_group 0;" ::: "memory"); }
        __syncthreads();
        if (kt + 2 < nkt) {
            int s2 = kt + 2; s2 = s2 - (s2 / NSTAGE) * NSTAGE;
            load(s2, kt + 2);
        }
        int s = kt - (kt / NSTAGE) * NSTAGE;
        uint32_t sb = sbase + (uint32_t)s * STAGE_B;

#pragma unroll
        for (int ks2 = 0; ks2 < 2; ks2++) {
            // jj index: bit0 -> (2tg vs 2tg+8), bit1 -> k16 half, bit2 -> hi/lo
            const int j0 = ks2 * 2;
            uint32_t ah[4][4], al[4][4];
#pragma unroll
            for (int mi = 0; mi < 4; mi++) {
                uint32_t r0 = sb + rowA[mi][0], r1 = sb + rowA[mi][1];
                ah[mi][0] = lds32(r0 + col[j0]);     ah[mi][1] = lds32(r1 + col[j0]);
                ah[mi][2] = lds32(r0 + col[j0 + 1]); ah[mi][3] = lds32(r1 + col[j0 + 1]);
                al[mi][0] = lds32(r0 + col[j0 + 4]); al[mi][1] = lds32(r1 + col[j0 + 4]);
                al[mi][2] = lds32(r0 + col[j0 + 5]); al[mi][3] = lds32(r1 + col[j0 + 5]);
            }
            uint32_t bh[4][2], bl[4][2];
#pragma unroll
            for (int ni = 0; ni < 4; ni++) {
                uint32_t rb = sb + rowB[ni];
                bh[ni][0] = lds32(rb + col[j0]);     bh[ni][1] = lds32(rb + col[j0 + 1]);
                bl[ni][0] = lds32(rb + col[j0 + 4]); bl[ni][1] = lds32(rb + col[j0 + 5]);
            }
#pragma unroll
            for (int mi = 0; mi < 4; mi++)
#pragma unroll
                for (int ni = 0; ni < 4; ni++) {
                    mma16(acc[mi][ni], al[mi], bh[ni]);
                    mma16(acc[mi][ni], ah[mi], bl[ni]);
                    mma16(acc[mi][ni], ah[mi], bh[ni]);
                }
        }
    }

    // ---- epilogue: write split-K partials ----
    float* outp = g_part + (size_t)ks * MDIM * NDIM;
#pragma unroll
    for (int mi = 0; mi < 4; mi++) {
        int r = mt * BM + wm * 64 + mi * 16 + g;
#pragma unroll
        for (int ni = 0; ni < 4; ni++) {
            int c = nt * BN + wn * 32 + ni * 8 + 2 * tg;
            *(float2*)&outp[(size_t)r * NDIM + c] =
                make_float2(acc[mi][ni][0], acc[mi][ni][1]);
            *(float2*)&outp[(size_t)(r + 8) * NDIM + c] =
                make_float2(acc[mi][ni][2], acc[mi][ni][3]);
        }
    }
}

// ============ split-K reduce + ReLU + LayerNorm(ddof=1) over D ============
__global__ void reduce_ln() {
    int row = blockIdx.x, tid = threadIdx.x;
    float v[4], s = 0.f, ss = 0.f;
#pragma unroll
    for (int j = 0; j < 4; j++) {
        int col = tid + j * 256;
        float a = 0.f;
#pragma unroll
        for (int sk = 0; sk < SPLITK; sk++)
            a += g_part[((size_t)sk * MDIM + row) * NDIM + col];
        a = fmaxf(a, 0.f);
        v[j] = a; s += a; ss += a * a;
    }
    __shared__ float r1[8], r2[8];
#pragma unroll
    for (int o = 16; o > 0; o >>= 1) {
        s  += __shfl_xor_sync(0xffffffffu, s, o);
        ss += __shfl_xor_sync(0xffffffffu, ss, o);
    }
    if ((tid & 31) == 0) { r1[tid >> 5] = s; r2[tid >> 5] = ss; }
    __syncthreads();
    if (tid == 0) {
        float S = 0.f, SS = 0.f;
        for (int w = 0; w < 8; w++) { S += r1[w]; SS += r2[w]; }
        r1[0] = S; r2[0] = SS;
    }
    __syncthreads();
    float mean = r1[0] * (1.f / 1024.f);
    float var  = (r2[0] - 1024.f * mean * mean) * (1.f / 1023.f);
    float inv  = 1.f / (sqrtf(fmaxf(var, 0.f)) + 1e-6f);
#pragma unroll
    for (int j = 0; j < 4; j++)
        g_xqn[row * NDIM + tid + j * 256] = (v[j] - mean) * inv;
}

// ============ attention tail: 3 iterations + final normalize ============
__global__ void __launch_bounds__(1024) attn_k(
    const float* __restrict__ qlw, const float* __restrict__ qlb,
    const float* __restrict__ n1a, const float* __restrict__ n1b,
    const float* __restrict__ n2a, const float* __restrict__ n2b,
    const float* __restrict__ fw1, const float* __restrict__ fb1,
    const float* __restrict__ fw2, const float* __restrict__ fb2,
    float* __restrict__ out)
{
    const int b = blockIdx.x, tid = threadIdx.x;
    const int h = tid >> 6, d = tid & 63;     // 16 x 64
    const int h2 = tid >> 5, t2 = tid & 31;   // 16 x 32 (tid < 512)

    __shared__ float qS[1024], qhS[1024], q_S[1024], zS[1024];
    __shared__ float scS[16 * 32], hidS[16 * 32];
    __shared__ float muS[16], isdS[16], redA[32];

    qS[tid] = g_xqn[(b * 32 + 16) * NDIM + tid];   // q = xq[:, t/2, :]
    __syncthreads();

    for (int i = 0; i < 3; i++) {
        {
            const float4* W4 = (const float4*)(qlw + ((size_t)i * 1024 + tid) * 1024);
            float acc = qlb[i * 1024 + tid];
#pragma unroll 8
            for (int k4 = 0; k4 < 256; k4++) {
                float4 w = W4[k4];
                acc += w.x * qS[k4 * 4] + w.y * qS[k4 * 4 + 1]
                     + w.z * qS[k4 * 4 + 2] + w.w * qS[k4 * 4 + 3];
            }
            qhS[tid] = fmaxf(acc, 0.f);
        }
        __syncthreads();

        if (tid < 512) {
            const float* khp = g_xqn + (b * 32 + t2) * NDIM + h2 * 64;
            const float* qp  = qhS + h2 * 64;
            float dot = 0.f;
#pragma unroll
            for (int dd = 0; dd < 64; dd++) dot += qp[dd] * khp[dd];
            dot *= 0.125f;
            float m = dot;
#pragma unroll
            for (int o = 16; o > 0; o >>= 1) m = fmaxf(m, __shfl_xor_sync(0xffffffffu, m, o));
            float e = __expf(dot - m);
            float sum = e;
#pragma unroll
            for (int o = 16; o > 0; o >>= 1) sum += __shfl_xor_sync(0xffffffffu, sum, o);
            scS[h2 * 32 + t2] = e / sum;
        }
        __syncthreads();

        {
            float a = 0.f;
            const float* vb = g_xqn + (size_t)(b * 32) * NDIM + h * 64 + d;
#pragma unroll
            for (int tt = 0; tt < 32; tt++) a += scS[h * 32 + tt] * vb[tt * NDIM];
            float z = a + qhS[tid];
            zS[tid] = z;
            __syncthreads();
            if (tid < 16) {
                float s = 0.f, ssum = 0.f;
                for (int dd = 0; dd < 64; dd++) {
                    float v = zS[tid * 64 + dd]; s += v; ssum += v * v;
                }
                float mu = s * (1.f / 64.f);
                float var = (ssum - 64.f * mu * mu) * (1.f / 63.f);
                muS[tid] = mu;
                isdS[tid] = 1.f / (sqrtf(fmaxf(var, 0.f)) + 1e-6f);
            }
            __syncthreads();
            q_S[tid] = n1a[(i * 16 + h) * 64 + d] * (z - muS[h]) * isdS[h]
                     + n1b[(i * 16 + h) * 64 + d];
        }
        __syncthreads();

        if (tid < 512) {
            const float* w1 = fw1 + ((size_t)(i * 16 + h2) * 32 + t2) * 64;
            float acc = fb1[(i * 16 + h2) * 32 + t2];
#pragma unroll
            for (int dd = 0; dd < 64; dd++) acc += q_S[h2 * 64 + dd] * w1[dd];
            hidS[h2 * 32 + t2] = fmaxf(acc, 0.f);
        }
        __syncthreads();

        {
            const float* w2 = fw2 + ((size_t)(i * 16 + h) * 64 + d) * 32;
            float acc = fb2[(i * 16 + h) * 64 + d];
#pragma unroll
            for (int ff = 0; ff < 32; ff++) acc += hidS[h * 32 + ff] * w2[ff];
            float z = q_S[tid] + acc;
            __syncthreads();
            zS[tid] = z;
            __syncthreads();
            if (tid < 16) {
                float s = 0.f, ssum = 0.f;
                for (int dd = 0; dd < 64; dd++) {
                    float v = zS[tid * 64 + dd]; s += v; ssum += v * v;
                }
                float mu = s * (1.f / 64.f);
                float var = (ssum - 64.f * mu * mu) * (1.f / 63.f);
                muS[tid] = mu;
                isdS[tid] = 1.f / (sqrtf(fmaxf(var, 0.f)) + 1e-6f);
            }
            __syncthreads();
            qS[tid] = n2a[(i * 16 + h) * 64 + d] * (z - muS[h]) * isdS[h]
                    + n2b[(i * 16 + h) * 64 + d];
        }
        __syncthreads();
    }

    float v = qS[tid];
    float ssq = v * v;
#pragma unroll
    for (int o = 16; o > 0; o >>= 1) ssq += __shfl_xor_sync(0xffffffffu, ssq, o);
    if ((tid & 31) == 0) redA[tid >> 5] = ssq;
    __syncthreads();
    if (tid < 32) {
        float s2 = redA[tid];
#pragma unroll
        for (int o = 16; o > 0; o >>= 1) s2 += __shfl_xor_sync(0xffffffffu, s2, o);
        if (tid == 0) redA[0] = s2;
    }
    __syncthreads();
    float nrm = sqrtf(redA[0]);
    out[b * 1024 + tid] = v / fmaxf(nrm, 1e-12f);
}

// ================= launch =================
extern "C" void kernel_launch(void* const* d_in, const int* in_sizes, int n_in,
                              void* d_out, int out_size) {
    const float* x     = (const float*)d_in[0];
    const float* gamma = (const float*)d_in[1];
    const float* beta  = (const float*)d_in[2];
    const float* qpr   = (const float*)d_in[3];
    const float* qlw   = (const float*)d_in[4];
    const float* qlb   = (const float*)d_in[5];
    const float* n1a   = (const float*)d_in[6];
    const float* n1b   = (const float*)d_in[7];
    const float* n2a   = (const float*)d_in[8];
    const float* n2b   = (const float*)d_in[9];
    const float* fw1   = (const float*)d_in[10];
    const float* fb1   = (const float*)d_in[11];
    const float* fw2   = (const float*)d_in[12];
    const float* fb2   = (const float*)d_in[13];
    float* out = (float*)d_out;

    prep_scales<<<256, 256>>>(gamma, beta);
    prep_A<<<dim3(KDIM / 512, MDIM), 256>>>(x);
    prep_W<<<(NDIM * (KDIM / 512)), 256>>>(qpr);

    cudaFuncSetAttribute(gemm_k, cudaFuncAttributeMaxDynamicSharedMemorySize, SMEM_TOTAL);
    gemm_k<<<dim3(NDIM / BN, MDIM / BM, SPLITK), 256, SMEM_TOTAL>>>();

    reduce_ln<<<MDIM, 256>>>();
    attn_k<<<8, 1024>>>(qlw, qlb, n1a, n1b, n2a, n2b, fw1, fb1, fw2, fb2, out);
}

// round 4
// speedup vs baseline: 1.9635x; 1.5888x over previous
#include <cuda_runtime.h>
#include <cuda_bf16.h>
#include <cstdint>
#include <math.h>

// ---------------- problem constants ----------------
#define KDIM 100352          // 2048*49
#define MDIM 256             // b*t
#define NDIM 1024            // D = H*d
#define NF   2048
#define TT   32
#define SQRT_NF 45.254833995939045f
#define INV_SQRT_BN 0.9999950000374997f   // 1/sqrt(1+1e-5)

// ---------------- GEMM tiling ----------------
#define BM 128
#define BN 128
#define BK 32
#define NSTAGE 3
#define SPLITK 18
#define KTILES 3136          // KDIM/BK
#define CHUNK  175           // ceil(KTILES/SPLITK); last chunk = 161

// smem: per stage: A 128 rows x 128B (hi 64B | lo 64B) = 16KB, B same = 16KB
#define STAGE_B 32768
#define SMEM_TOTAL (NSTAGE * STAGE_B)   // 98304

// ---------------- scratch (allocation-free: device globals) ----------------
__device__ __nv_bfloat16 g_Ahi[(size_t)MDIM * KDIM];
__device__ __nv_bfloat16 g_Alo[(size_t)MDIM * KDIM];
__device__ __nv_bfloat16 g_Whi[(size_t)NDIM * KDIM];
__device__ __nv_bfloat16 g_Wlo[(size_t)NDIM * KDIM];
__device__ float g_part[(size_t)SPLITK * MDIM * NDIM]; // split-K partials
__device__ float g_xqn[MDIM * NDIM];                   // layernormed xq
__device__ float g_off[TT * NF];                       // beta*sqrtNF + pe[t][c]
__device__ float g_sc[NF];                             // per-channel scale
__device__ float g_q[8 * NDIM];                        // evolving q
__device__ float g_qh[8 * NDIM];                       // relu(q @ W^T + b)

// ================= prep: scales + positional encoding =================
__global__ void prep_scales(const float* __restrict__ gamma,
                            const float* __restrict__ beta) {
    int idx = blockIdx.x * 256 + threadIdx.x;      // 65536 = 32*2048
    int t = idx >> 11;
    int c = idx & (NF - 1);
    float w = __expf(-(2.0f * (float)c / (float)NF) * 9.210340371976184f); // ln(10000)
    float ang = (float)t * w;
    float pe = (c & 1) ? cosf(ang) : sinf(ang);
    g_off[idx] = beta[c] * SQRT_NF + pe;
    if (idx < NF) g_sc[idx] = gamma[idx] * SQRT_NF * INV_SQRT_BN;
}

// ========== prep A: affine + bf16 hi/lo split (4 elems/thread) ==========
__global__ void prep_A(const float* __restrict__ x) {
    int n = blockIdx.y;
    int k = (blockIdx.x * 256 + threadIdx.x) * 4;   // gridDim.x = KDIM/1024 = 98
    size_t id = (size_t)n * KDIM + k;
    float4 xv = *(const float4*)(x + id);
    int to = (n & 31) * NF;
    float a[4];
    a[0] = xv.x * g_sc[k / 49]       + g_off[to + k / 49];
    a[1] = xv.y * g_sc[(k + 1) / 49] + g_off[to + (k + 1) / 49];
    a[2] = xv.z * g_sc[(k + 2) / 49] + g_off[to + (k + 2) / 49];
    a[3] = xv.w * g_sc[(k + 3) / 49] + g_off[to + (k + 3) / 49];
    __nv_bfloat162 hv[2], lv[2];
#pragma unroll
    for (int j = 0; j < 2; j++) {
        __nv_bfloat16 h0 = __float2bfloat16(a[2 * j]);
        __nv_bfloat16 h1 = __float2bfloat16(a[2 * j + 1]);
        hv[j].x = h0; hv[j].y = h1;
        lv[j].x = __float2bfloat16(a[2 * j] - __bfloat162float(h0));
        lv[j].y = __float2bfloat16(a[2 * j + 1] - __bfloat162float(h1));
    }
    *(uint2*)(g_Ahi + id) = *(uint2*)hv;
    *(uint2*)(g_Alo + id) = *(uint2*)lv;
}

// ========== prep W: bf16 hi/lo split (4 elems/thread) ==========
__global__ void prep_W(const float* __restrict__ w) {
    size_t id = ((size_t)blockIdx.x * 256 + threadIdx.x) * 4;  // grid = 100352
    float4 wv = *(const float4*)(w + id);
    float a[4] = {wv.x, wv.y, wv.z, wv.w};
    __nv_bfloat162 hv[2], lv[2];
#pragma unroll
    for (int j = 0; j < 2; j++) {
        __nv_bfloat16 h0 = __float2bfloat16(a[2 * j]);
        __nv_bfloat16 h1 = __float2bfloat16(a[2 * j + 1]);
        hv[j].x = h0; hv[j].y = h1;
        lv[j].x = __float2bfloat16(a[2 * j] - __bfloat162float(h0));
        lv[j].y = __float2bfloat16(a[2 * j + 1] - __bfloat162float(h1));
    }
    *(uint2*)(g_Whi + id) = *(uint2*)hv;
    *(uint2*)(g_Wlo + id) = *(uint2*)lv;
}

// ================= bf16 3-product GEMM (mma.sync m16n8k16) =================
__device__ __forceinline__ void mma16(float* c, const uint32_t* a, const uint32_t* b) {
    asm volatile(
        "mma.sync.aligned.m16n8k16.row.col.f32.bf16.bf16.f32 "
        "{%0,%1,%2,%3},{%4,%5,%6,%7},{%8,%9},{%0,%1,%2,%3};"
        : "+f"(c[0]), "+f"(c[1]), "+f"(c[2]), "+f"(c[3])
        : "r"(a[0]), "r"(a[1]), "r"(a[2]), "r"(a[3]), "r"(b[0]), "r"(b[1]));
}
__device__ __forceinline__ uint32_t lds32(uint32_t a) {
    uint32_t v;
    asm volatile("ld.shared.b32 %0, [%1];" : "=r"(v) : "r"(a));
    return v;
}

__global__ void __launch_bounds__(256, 2) gemm_k() {
    extern __shared__ char smem[];
    const uint32_t sbase = (uint32_t)__cvta_generic_to_shared(smem);
    const int tid = threadIdx.x;
    const int lane = tid & 31, wid = tid >> 5;
    const int g = lane >> 2, tg = lane & 3;
    const int wm = wid >> 2, wn = wid & 3;          // 2x4 warps, tile 64x32
    const int nt = blockIdx.x, mt = blockIdx.y, ks = blockIdx.z;
    const int k0t = ks * CHUNK;
    int nkt = KTILES - k0t; if (nkt > CHUNK) nkt = CHUNK;
    const int k0 = k0t * BK;

    // ---- cp.async geometry: 1024 chunks of 16B each for A and B per stage ----
    const __nv_bfloat16* pA[4]; const __nv_bfloat16* pB[4];
    uint32_t dA[4], dB[4];
#pragma unroll
    for (int j = 0; j < 4; j++) {
        int c = tid + j * 256;
        int row = c >> 3, part = c & 7;
        int sub = (part < 4) ? part * 16 : 64 + (part & 3) * 16;
        uint32_t phys = (uint32_t)row * 128u + (uint32_t)(sub ^ ((row & 7) << 4));
        dA[j] = phys;                 // A region at stage base + 0
        dB[j] = 16384u + phys;        // B region at stage base + 16KB
        const __nv_bfloat16* ah = (part < 4) ? g_Ahi : g_Alo;
        const __nv_bfloat16* wh = (part < 4) ? g_Whi : g_Wlo;
        pA[j] = ah + (size_t)(mt * BM + row) * KDIM + k0 + (part & 3) * 8;
        pB[j] = wh + (size_t)(nt * BN + row) * KDIM + k0 + (part & 3) * 8;
    }

    auto load = [&](int s, int kt) {
        uint32_t sb = sbase + (uint32_t)s * STAGE_B;
        size_t koff = (size_t)kt * BK;
#pragma unroll
        for (int j = 0; j < 4; j++) {
            asm volatile("cp.async.cg.shared.global [%0], [%1], 16;"
                         :: "r"(sb + dA[j]), "l"(pA[j] + koff));
            asm volatile("cp.async.cg.shared.global [%0], [%1], 16;"
                         :: "r"(sb + dB[j]), "l"(pB[j] + koff));
        }
        asm volatile("cp.async.commit_group;" ::: "memory");
    };

    uint32_t col[8];
#pragma unroll
    for (int jj = 0; jj < 8; jj++) col[jj] = (uint32_t)(((jj ^ g) << 4) + tg * 4);
    uint32_t rowA[4][2], rowB[4];
#pragma unroll
    for (int mi = 0; mi < 4; mi++) {
        rowA[mi][0] = (uint32_t)(wm * 64 + mi * 16 + g) * 128u;
        rowA[mi][1] = rowA[mi][0] + 8u * 128u;
    }
#pragma unroll
    for (int ni = 0; ni < 4; ni++) rowB[ni] = (uint32_t)(wn * 32 + ni * 8 + g) * 128u + 16384u;

    float acc[4][4][4];
#pragma unroll
    for (int a = 0; a < 4; a++)
#pragma unroll
        for (int b = 0; b < 4; b++)
#pragma unroll
            for (int cc = 0; cc < 4; cc++) acc[a][b][cc] = 0.f;

    load(0, 0);
    load(1, 1);

    for (int kt = 0; kt < nkt; kt++) {
        if (kt + 1 < nkt) { asm volatile("cp.async.wait_group 1;" ::: "memory"); }
        else              { asm volatile("cp.async.wait_group 0;" ::: "memory"); }
        __syncthreads();
        if (kt + 2 < nkt) {
            int s2 = kt + 2; s2 = s2 - (s2 / NSTAGE) * NSTAGE;
            load(s2, kt + 2);
        }
        int s = kt - (kt / NSTAGE) * NSTAGE;
        uint32_t sb = sbase + (uint32_t)s * STAGE_B;

#pragma unroll
        for (int ks2 = 0; ks2 < 2; ks2++) {
            const int j0 = ks2 * 2;
            uint32_t ah[4][4], al[4][4];
#pragma unroll
            for (int mi = 0; mi < 4; mi++) {
                uint32_t r0 = sb + rowA[mi][0], r1 = sb + rowA[mi][1];
                ah[mi][0] = lds32(r0 + col[j0]);     ah[mi][1] = lds32(r1 + col[j0]);
                ah[mi][2] = lds32(r0 + col[j0 + 1]); ah[mi][3] = lds32(r1 + col[j0 + 1]);
                al[mi][0] = lds32(r0 + col[j0 + 4]); al[mi][1] = lds32(r1 + col[j0 + 4]);
                al[mi][2] = lds32(r0 + col[j0 + 5]); al[mi][3] = lds32(r1 + col[j0 + 5]);
            }
            uint32_t bh[4][2], bl[4][2];
#pragma unroll
            for (int ni = 0; ni < 4; ni++) {
                uint32_t rb = sb + rowB[ni];
                bh[ni][0] = lds32(rb + col[j0]);     bh[ni][1] = lds32(rb + col[j0 + 1]);
                bl[ni][0] = lds32(rb + col[j0 + 4]); bl[ni][1] = lds32(rb + col[j0 + 5]);
            }
#pragma unroll
            for (int mi = 0; mi < 4; mi++)
#pragma unroll
                for (int ni = 0; ni < 4; ni++) {
                    mma16(acc[mi][ni], al[mi], bh[ni]);
                    mma16(acc[mi][ni], ah[mi], bl[ni]);
                    mma16(acc[mi][ni], ah[mi], bh[ni]);
                }
        }
    }

    float* outp = g_part + (size_t)ks * MDIM * NDIM;
#pragma unroll
    for (int mi = 0; mi < 4; mi++) {
        int r = mt * BM + wm * 64 + mi * 16 + g;
#pragma unroll
        for (int ni = 0; ni < 4; ni++) {
            int c = nt * BN + wn * 32 + ni * 8 + 2 * tg;
            *(float2*)&outp[(size_t)r * NDIM + c] =
                make_float2(acc[mi][ni][0], acc[mi][ni][1]);
            *(float2*)&outp[(size_t)(r + 8) * NDIM + c] =
                make_float2(acc[mi][ni][2], acc[mi][ni][3]);
        }
    }
}

// ============ split-K reduce + ReLU + LayerNorm(ddof=1) over D ============
__global__ void reduce_ln() {
    int row = blockIdx.x, tid = threadIdx.x;
    float v[4], s = 0.f, ss = 0.f;
#pragma unroll
    for (int j = 0; j < 4; j++) {
        int col = tid + j * 256;
        float a = 0.f;
#pragma unroll
        for (int sk = 0; sk < SPLITK; sk++)
            a += g_part[((size_t)sk * MDIM + row) * NDIM + col];
        a = fmaxf(a, 0.f);
        v[j] = a; s += a; ss += a * a;
    }
    __shared__ float r1[8], r2[8];
#pragma unroll
    for (int o = 16; o > 0; o >>= 1) {
        s  += __shfl_xor_sync(0xffffffffu, s, o);
        ss += __shfl_xor_sync(0xffffffffu, ss, o);
    }
    if ((tid & 31) == 0) { r1[tid >> 5] = s; r2[tid >> 5] = ss; }
    __syncthreads();
    if (tid == 0) {
        float S = 0.f, SS = 0.f;
        for (int w = 0; w < 8; w++) { S += r1[w]; SS += r2[w]; }
        r1[0] = S; r2[0] = SS;
    }
    __syncthreads();
    float mean = r1[0] * (1.f / 1024.f);
    float var  = (r2[0] - 1024.f * mean * mean) * (1.f / 1023.f);
    float inv  = 1.f / (sqrtf(fmaxf(var, 0.f)) + 1e-6f);
#pragma unroll
    for (int j = 0; j < 4; j++)
        g_xqn[row * NDIM + tid + j * 256] = (v[j] - mean) * inv;
}

// ============ qh = relu(q @ qlin_w[i].T + qlin_b[i]), 128 blocks ============
__global__ void __launch_bounds__(256) gemv_k(
    const float* __restrict__ qlw, const float* __restrict__ qlb,
    const float* __restrict__ qsrc, int qrowstride, int qoff, int i)
{
    const int b = blockIdx.y, c = blockIdx.x;     // grid (16, 8)
    const int tid = threadIdx.x;
    const int o = c * 64 + (tid >> 2);            // output index
    const int part = tid & 3;

    __shared__ float qS[1024];
    const float* qp = qsrc + (size_t)b * qrowstride + qoff;
#pragma unroll
    for (int j = tid; j < 1024; j += 256) qS[j] = qp[j];
    __syncthreads();

    const float4* W4 = (const float4*)(qlw + ((size_t)i * 1024 + o) * 1024 + part * 256);
    const float* qb = qS + part * 256;
    float acc = 0.f;
#pragma unroll 8
    for (int j = 0; j < 64; j++) {
        float4 w = W4[j];
        acc += w.x * qb[j * 4] + w.y * qb[j * 4 + 1]
             + w.z * qb[j * 4 + 2] + w.w * qb[j * 4 + 3];
    }
    acc += __shfl_xor_sync(0xffffffffu, acc, 1);
    acc += __shfl_xor_sync(0xffffffffu, acc, 2);
    if (part == 0) g_qh[b * 1024 + o] = fmaxf(acc + qlb[i * 1024 + o], 0.f);
}

// ============ attention rest: softmax + AV + norms + FFN ============
__global__ void __launch_bounds__(1024) rest_k(
    const float* __restrict__ n1a, const float* __restrict__ n1b,
    const float* __restrict__ n2a, const float* __restrict__ n2b,
    const float* __restrict__ fw1, const float* __restrict__ fb1,
    const float* __restrict__ fw2, const float* __restrict__ fb2,
    int i, int last, float* __restrict__ out)
{
    const int b = blockIdx.x, tid = threadIdx.x;
    const int h = tid >> 6, d = tid & 63;     // 16 x 64
    const int h2 = tid >> 5, t2 = tid & 31;   // 16 x 32 (tid < 512)

    __shared__ float qhS[1024], q_S[1024], zS[1024];
    __shared__ float scS[16 * 32], hidS[16 * 32];
    __shared__ float muS[16], isdS[16], redA[32];

    qhS[tid] = g_qh[b * 1024 + tid];
    __syncthreads();

    // scores + softmax: one warp per head, one lane per t
    if (tid < 512) {
        const float* khp = g_xqn + (b * 32 + t2) * NDIM + h2 * 64;
        const float* qp  = qhS + h2 * 64;
        float dot = 0.f;
#pragma unroll
        for (int dd = 0; dd < 64; dd++) dot += qp[dd] * khp[dd];
        dot *= 0.125f;
        float m = dot;
#pragma unroll
        for (int o = 16; o > 0; o >>= 1) m = fmaxf(m, __shfl_xor_sync(0xffffffffu, m, o));
        float e = __expf(dot - m);
        float sum = e;
#pragma unroll
        for (int o = 16; o > 0; o >>= 1) sum += __shfl_xor_sync(0xffffffffu, sum, o);
        scS[h2 * 32 + t2] = e / sum;
    }
    __syncthreads();

    // A = sc @ vh ; z = A + qh ; q_ = norm1(z)
    {
        float a = 0.f;
        const float* vb = g_xqn + (size_t)(b * 32) * NDIM + h * 64 + d;
#pragma unroll
        for (int tt = 0; tt < 32; tt++) a += scS[h * 32 + tt] * vb[tt * NDIM];
        float z = a + qhS[tid];
        zS[tid] = z;
        __syncthreads();
        if (tid < 16) {
            float s = 0.f, ssum = 0.f;
            for (int dd = 0; dd < 64; dd++) {
                float v = zS[tid * 64 + dd]; s += v; ssum += v * v;
            }
            float mu = s * (1.f / 64.f);
            float var = (ssum - 64.f * mu * mu) * (1.f / 63.f);
            muS[tid] = mu;
            isdS[tid] = 1.f / (sqrtf(fmaxf(var, 0.f)) + 1e-6f);
        }
        __syncthreads();
        q_S[tid] = n1a[(i * 16 + h) * 64 + d] * (zS[tid] - muS[h]) * isdS[h]
                 + n1b[(i * 16 + h) * 64 + d];
    }
    __syncthreads();

    // hid = relu(q_ @ ff_w1[i] + b1)
    if (tid < 512) {
        const float* w1 = fw1 + ((size_t)(i * 16 + h2) * 32 + t2) * 64;
        float acc = fb1[(i * 16 + h2) * 32 + t2];
#pragma unroll
        for (int dd = 0; dd < 64; dd++) acc += q_S[h2 * 64 + dd] * w1[dd];
        hidS[h2 * 32 + t2] = fmaxf(acc, 0.f);
    }
    __syncthreads();

    // ffo = hid @ ff_w2[i] + b2 ; q = norm2(q_ + ffo)
    float qv;
    {
        const float* w2 = fw2 + ((size_t)(i * 16 + h) * 64 + d) * 32;
        float acc = fb2[(i * 16 + h) * 64 + d];
#pragma unroll
        for (int ff = 0; ff < 32; ff++) acc += hidS[h * 32 + ff] * w2[ff];
        float z = q_S[tid] + acc;
        __syncthreads();
        zS[tid] = z;
        __syncthreads();
        if (tid < 16) {
            float s = 0.f, ssum = 0.f;
            for (int dd = 0; dd < 64; dd++) {
                float v = zS[tid * 64 + dd]; s += v; ssum += v * v;
            }
            float mu = s * (1.f / 64.f);
            float var = (ssum - 64.f * mu * mu) * (1.f / 63.f);
            muS[tid] = mu;
            isdS[tid] = 1.f / (sqrtf(fmaxf(var, 0.f)) + 1e-6f);
        }
        __syncthreads();
        qv = n2a[(i * 16 + h) * 64 + d] * (zS[tid] - muS[h]) * isdS[h]
           + n2b[(i * 16 + h) * 64 + d];
    }

    if (!last) {
        g_q[b * 1024 + tid] = qv;
        return;
    }

    // f = q / max(||q||, 1e-12)
    float ssq = qv * qv;
#pragma unroll
    for (int o = 16; o > 0; o >>= 1) ssq += __shfl_xor_sync(0xffffffffu, ssq, o);
    if ((tid & 31) == 0) redA[tid >> 5] = ssq;
    __syncthreads();
    if (tid < 32) {
        float s2 = redA[tid];
#pragma unroll
        for (int o = 16; o > 0; o >>= 1) s2 += __shfl_xor_sync(0xffffffffu, s2, o);
        if (tid == 0) redA[0] = s2;
    }
    __syncthreads();
    float nrm = sqrtf(redA[0]);
    out[b * 1024 + tid] = qv / fmaxf(nrm, 1e-12f);
}

// ================= launch =================
extern "C" void kernel_launch(void* const* d_in, const int* in_sizes, int n_in,
                              void* d_out, int out_size) {
    const float* x     = (const float*)d_in[0];
    const float* gamma = (const float*)d_in[1];
    const float* beta  = (const float*)d_in[2];
    const float* qpr   = (const float*)d_in[3];
    const float* qlw   = (const float*)d_in[4];
    const float* qlb   = (const float*)d_in[5];
    const float* n1a   = (const float*)d_in[6];
    const float* n1b   = (const float*)d_in[7];
    const float* n2a   = (const float*)d_in[8];
    const float* n2b   = (const float*)d_in[9];
    const float* fw1   = (const float*)d_in[10];
    const float* fb1   = (const float*)d_in[11];
    const float* fw2   = (const float*)d_in[12];
    const float* fb2   = (const float*)d_in[13];
    float* out = (float*)d_out;

    prep_scales<<<256, 256>>>(gamma, beta);
    prep_A<<<dim3(KDIM / 1024, MDIM), 256>>>(x);
    prep_W<<<(NDIM * KDIM / 1024), 256>>>(qpr);

    cudaFuncSetAttribute(gemm_k, cudaFuncAttributeMaxDynamicSharedMemorySize, SMEM_TOTAL);
    gemm_k<<<dim3(NDIM / BN, MDIM / BM, SPLITK), 256, SMEM_TOTAL>>>();

    reduce_ln<<<MDIM, 256>>>();

    float* g_xqn_p = nullptr;
    float* g_q_p = nullptr;
    cudaGetSymbolAddress((void**)&g_xqn_p, g_xqn);
    cudaGetSymbolAddress((void**)&g_q_p, g_q);

    for (int i = 0; i < 3; i++) {
        if (i == 0)
            gemv_k<<<dim3(16, 8), 256>>>(qlw, qlb, g_xqn_p, 32 * NDIM, 16 * NDIM, 0);
        else
            gemv_k<<<dim3(16, 8), 256>>>(qlw, qlb, g_q_p, NDIM, 0, i);
        rest_k<<<8, 1024>>>(n1a, n1b, n2a, n2b, fw1, fb1, fw2, fb2,
                            i, (i == 2) ? 1 : 0, out);
    }
}

// round 5
// speedup vs baseline: 3.1152x; 1.5865x over previous
#include <cuda_runtime.h>
#include <cuda_fp16.h>
#include <cstdint>
#include <math.h>

// ---------------- problem constants ----------------
#define KDIM 100352          // 2048*49
#define MDIM 256             // b*t
#define NDIM 1024            // D = H*d
#define NF   2048
#define TT   32
#define SQRT_NF 45.254833995939045f
#define INV_SQRT_BN 0.9999950000374997f   // 1/sqrt(1+1e-5)

// ---------------- GEMM tiling ----------------
#define BM 128
#define BN 128
#define BK 64                // 64 fp16 = 128 bytes = one smem row
#define NSTAGE 3
#define SPLITK 18
#define KTILES 1568          // KDIM/BK
#define CHUNK  88            // ceil(KTILES/SPLITK); last chunk = 72

// per stage: A 128 rows x 128B = 16KB, B same
#define STAGE_B 32768
#define SMEM_TOTAL (NSTAGE * STAGE_B)   // 98304

// ---------------- scratch (allocation-free: device globals) ----------------
__device__ __half g_Ah[(size_t)MDIM * KDIM];
__device__ __half g_Wh[(size_t)NDIM * KDIM];
__device__ float g_part[(size_t)SPLITK * MDIM * NDIM]; // split-K partials
__device__ float g_xqn[MDIM * NDIM];                   // layernormed xq
__device__ float g_off[TT * NF];                       // beta*sqrtNF + pe[t][c]
__device__ float g_sc[NF];                             // per-channel scale
__device__ float g_q[8 * NDIM];                        // evolving q
__device__ float g_qh[8 * NDIM];                       // relu(q @ W^T + b)

// ================= prep: scales + positional encoding =================
__global__ void prep_scales(const float* __restrict__ gamma,
                            const float* __restrict__ beta) {
    int idx = blockIdx.x * 256 + threadIdx.x;      // 65536 = 32*2048
    int t = idx >> 11;
    int c = idx & (NF - 1);
    float w = __expf(-(2.0f * (float)c / (float)NF) * 9.210340371976184f); // ln(10000)
    float ang = (float)t * w;
    float pe = (c & 1) ? cosf(ang) : sinf(ang);
    g_off[idx] = beta[c] * SQRT_NF + pe;
    if (idx < NF) g_sc[idx] = gamma[idx] * SQRT_NF * INV_SQRT_BN;
}

// ========== prep A: affine -> fp16 (4 elems/thread) ==========
__global__ void prep_A(const float* __restrict__ x) {
    int n = blockIdx.y;
    int k = (blockIdx.x * 256 + threadIdx.x) * 4;   // gridDim.x = KDIM/1024 = 98
    size_t id = (size_t)n * KDIM + k;
    float4 xv = *(const float4*)(x + id);
    int to = (n & 31) * NF;
    __half2 hv[2];
    hv[0] = __floats2half2_rn(xv.x * g_sc[k / 49]       + g_off[to + k / 49],
                              xv.y * g_sc[(k + 1) / 49] + g_off[to + (k + 1) / 49]);
    hv[1] = __floats2half2_rn(xv.z * g_sc[(k + 2) / 49] + g_off[to + (k + 2) / 49],
                              xv.w * g_sc[(k + 3) / 49] + g_off[to + (k + 3) / 49]);
    *(uint2*)(g_Ah + id) = *(uint2*)hv;
}

// ========== prep W: fp32 -> fp16 (4 elems/thread) ==========
__global__ void prep_W(const float* __restrict__ w) {
    size_t id = ((size_t)blockIdx.x * 256 + threadIdx.x) * 4;  // grid = 100352
    float4 wv = *(const float4*)(w + id);
    __half2 hv[2];
    hv[0] = __floats2half2_rn(wv.x, wv.y);
    hv[1] = __floats2half2_rn(wv.z, wv.w);
    *(uint2*)(g_Wh + id) = *(uint2*)hv;
}

// ================= fp16 GEMM (mma.sync m16n8k16, fp32 accum) =================
__device__ __forceinline__ void mma16(float* c, const uint32_t* a, const uint32_t* b) {
    asm volatile(
        "mma.sync.aligned.m16n8k16.row.col.f32.f16.f16.f32 "
        "{%0,%1,%2,%3},{%4,%5,%6,%7},{%8,%9},{%0,%1,%2,%3};"
        : "+f"(c[0]), "+f"(c[1]), "+f"(c[2]), "+f"(c[3])
        : "r"(a[0]), "r"(a[1]), "r"(a[2]), "r"(a[3]), "r"(b[0]), "r"(b[1]));
}
__device__ __forceinline__ uint32_t lds32(uint32_t a) {
    uint32_t v;
    asm volatile("ld.shared.b32 %0, [%1];" : "=r"(v) : "r"(a));
    return v;
}

__global__ void __launch_bounds__(256, 2) gemm_k() {
    extern __shared__ char smem[];
    const uint32_t sbase = (uint32_t)__cvta_generic_to_shared(smem);
    const int tid = threadIdx.x;
    const int lane = tid & 31, wid = tid >> 5;
    const int g = lane >> 2, tg = lane & 3;
    const int wm = wid >> 2, wn = wid & 3;          // 2x4 warps, tile 64x32
    const int nt = blockIdx.x, mt = blockIdx.y, ks = blockIdx.z;
    const int k0t = ks * CHUNK;
    int nkt = KTILES - k0t; if (nkt > CHUNK) nkt = CHUNK;
    const int k0 = k0t * BK;

    // ---- cp.async geometry: 1024 chunks of 16B for A and for B per stage ----
    const __half* pA[4]; const __half* pB[4];
    uint32_t dA[4], dB[4];
#pragma unroll
    for (int j = 0; j < 4; j++) {
        int c = tid + j * 256;
        int row = c >> 3, part = c & 7;            // 8 x 16B chunks per 128B row
        uint32_t phys = (uint32_t)row * 128u + (uint32_t)((part * 16) ^ ((row & 7) << 4));
        dA[j] = phys;                 // A region at stage base + 0
        dB[j] = 16384u + phys;        // B region at stage base + 16KB
        pA[j] = g_Ah + (size_t)(mt * BM + row) * KDIM + k0 + part * 8;
        pB[j] = g_Wh + (size_t)(nt * BN + row) * KDIM + k0 + part * 8;
    }

    auto load = [&](int s, int kt) {
        uint32_t sb = sbase + (uint32_t)s * STAGE_B;
        size_t koff = (size_t)kt * BK;
#pragma unroll
        for (int j = 0; j < 4; j++) {
            asm volatile("cp.async.cg.shared.global [%0], [%1], 16;"
                         :: "r"(sb + dA[j]), "l"(pA[j] + koff));
            asm volatile("cp.async.cg.shared.global [%0], [%1], 16;"
                         :: "r"(sb + dB[j]), "l"(pB[j] + koff));
        }
        asm volatile("cp.async.commit_group;" ::: "memory");
    };

    // fragment columns: byte = jj*16 + tg*4 logical, swizzled by row&7 == g
    uint32_t col[8];
#pragma unroll
    for (int jj = 0; jj < 8; jj++) col[jj] = (uint32_t)(((jj ^ g) << 4) + tg * 4);
    uint32_t rowA[4][2], rowB[4];
#pragma unroll
    for (int mi = 0; mi < 4; mi++) {
        rowA[mi][0] = (uint32_t)(wm * 64 + mi * 16 + g) * 128u;
        rowA[mi][1] = rowA[mi][0] + 8u * 128u;
    }
#pragma unroll
    for (int ni = 0; ni < 4; ni++) rowB[ni] = (uint32_t)(wn * 32 + ni * 8 + g) * 128u + 16384u;

    float acc[4][4][4];
#pragma unroll
    for (int a = 0; a < 4; a++)
#pragma unroll
        for (int b = 0; b < 4; b++)
#pragma unroll
            for (int cc = 0; cc < 4; cc++) acc[a][b][cc] = 0.f;

    load(0, 0);
    load(1, 1);

    for (int kt = 0; kt < nkt; kt++) {
        if (kt + 1 < nkt) { asm volatile("cp.async.wait_group 1;" ::: "memory"); }
        else              { asm volatile("cp.async.wait_group 0;" ::: "memory"); }
        __syncthreads();
        if (kt + 2 < nkt) {
            int s2 = kt + 2; s2 = s2 - (s2 / NSTAGE) * NSTAGE;
            load(s2, kt + 2);
        }
        int s = kt - (kt / NSTAGE) * NSTAGE;
        uint32_t sb = sbase + (uint32_t)s * STAGE_B;

#pragma unroll
        for (int ks2 = 0; ks2 < 4; ks2++) {          // 4 x k16 per BK=64 row
            const int j0 = ks2 * 2;
            uint32_t ah[4][4];
#pragma unroll
            for (int mi = 0; mi < 4; mi++) {
                uint32_t r0 = sb + rowA[mi][0], r1 = sb + rowA[mi][1];
                ah[mi][0] = lds32(r0 + col[j0]);     ah[mi][1] = lds32(r1 + col[j0]);
                ah[mi][2] = lds32(r0 + col[j0 + 1]); ah[mi][3] = lds32(r1 + col[j0 + 1]);
            }
            uint32_t bh[4][2];
#pragma unroll
            for (int ni = 0; ni < 4; ni++) {
                uint32_t rb = sb + rowB[ni];
                bh[ni][0] = lds32(rb + col[j0]);     bh[ni][1] = lds32(rb + col[j0 + 1]);
            }
#pragma unroll
            for (int mi = 0; mi < 4; mi++)
#pragma unroll
                for (int ni = 0; ni < 4; ni++)
                    mma16(acc[mi][ni], ah[mi], bh[ni]);
        }
    }

    float* outp = g_part + (size_t)ks * MDIM * NDIM;
#pragma unroll
    for (int mi = 0; mi < 4; mi++) {
        int r = mt * BM + wm * 64 + mi * 16 + g;
#pragma unroll
        for (int ni = 0; ni < 4; ni++) {
            int c = nt * BN + wn * 32 + ni * 8 + 2 * tg;
            *(float2*)&outp[(size_t)r * NDIM + c] =
                make_float2(acc[mi][ni][0], acc[mi][ni][1]);
            *(float2*)&outp[(size_t)(r + 8) * NDIM + c] =
                make_float2(acc[mi][ni][2], acc[mi][ni][3]);
        }
    }
}

// ============ split-K reduce + ReLU + LayerNorm(ddof=1) over D ============
__global__ void reduce_ln() {
    int row = blockIdx.x, tid = threadIdx.x;
    float v[4], s = 0.f, ss = 0.f;
#pragma unroll
    for (int j = 0; j < 4; j++) {
        int col = tid + j * 256;
        float a = 0.f;
#pragma unroll
        for (int sk = 0; sk < SPLITK; sk++)
            a += g_part[((size_t)sk * MDIM + row) * NDIM + col];
        a = fmaxf(a, 0.f);
        v[j] = a; s += a; ss += a * a;
    }
    __shared__ float r1[8], r2[8];
#pragma unroll
    for (int o = 16; o > 0; o >>= 1) {
        s  += __shfl_xor_sync(0xffffffffu, s, o);
        ss += __shfl_xor_sync(0xffffffffu, ss, o);
    }
    if ((tid & 31) == 0) { r1[tid >> 5] = s; r2[tid >> 5] = ss; }
    __syncthreads();
    if (tid == 0) {
        float S = 0.f, SS = 0.f;
        for (int w = 0; w < 8; w++) { S += r1[w]; SS += r2[w]; }
        r1[0] = S; r2[0] = SS;
    }
    __syncthreads();
    float mean = r1[0] * (1.f / 1024.f);
    float var  = (r2[0] - 1024.f * mean * mean) * (1.f / 1023.f);
    float inv  = 1.f / (sqrtf(fmaxf(var, 0.f)) + 1e-6f);
#pragma unroll
    for (int j = 0; j < 4; j++)
        g_xqn[row * NDIM + tid + j * 256] = (v[j] - mean) * inv;
}

// ============ qh = relu(q @ qlin_w[i].T + qlin_b[i]), 128 blocks ============
__global__ void __launch_bounds__(256) gemv_k(
    const float* __restrict__ qlw, const float* __restrict__ qlb,
    const float* __restrict__ qsrc, int qrowstride, int qoff, int i)
{
    const int b = blockIdx.y, c = blockIdx.x;     // grid (16, 8)
    const int tid = threadIdx.x;
    const int o = c * 64 + (tid >> 2);            // output index
    const int part = tid & 3;

    __shared__ float qS[1024];
    const float* qp = qsrc + (size_t)b * qrowstride + qoff;
#pragma unroll
    for (int j = tid; j < 1024; j += 256) qS[j] = qp[j];
    __syncthreads();

    const float4* W4 = (const float4*)(qlw + ((size_t)i * 1024 + o) * 1024 + part * 256);
    const float* qb = qS + part * 256;
    float acc = 0.f;
#pragma unroll 8
    for (int j = 0; j < 64; j++) {
        float4 w = W4[j];
        acc += w.x * qb[j * 4] + w.y * qb[j * 4 + 1]
             + w.z * qb[j * 4 + 2] + w.w * qb[j * 4 + 3];
    }
    acc += __shfl_xor_sync(0xffffffffu, acc, 1);
    acc += __shfl_xor_sync(0xffffffffu, acc, 2);
    if (part == 0) g_qh[b * 1024 + o] = fmaxf(acc + qlb[i * 1024 + o], 0.f);
}

// ============ attention rest: softmax + AV + norms + FFN ============
__global__ void __launch_bounds__(1024) rest_k(
    const float* __restrict__ n1a, const float* __restrict__ n1b,
    const float* __restrict__ n2a, const float* __restrict__ n2b,
    const float* __restrict__ fw1, const float* __restrict__ fb1,
    const float* __restrict__ fw2, const float* __restrict__ fb2,
    int i, int last, float* __restrict__ out)
{
    const int b = blockIdx.x, tid = threadIdx.x;
    const int h = tid >> 6, d = tid & 63;     // 16 x 64
    const int h2 = tid >> 5, t2 = tid & 31;   // 16 x 32 (tid < 512)

    __shared__ float qhS[1024], q_S[1024], zS[1024];
    __shared__ float scS[16 * 32], hidS[16 * 32];
    __shared__ float muS[16], isdS[16], redA[32];

    qhS[tid] = g_qh[b * 1024 + tid];
    __syncthreads();

    if (tid < 512) {
        const float* khp = g_xqn + (b * 32 + t2) * NDIM + h2 * 64;
        const float* qp  = qhS + h2 * 64;
        float dot = 0.f;
#pragma unroll
        for (int dd = 0; dd < 64; dd++) dot += qp[dd] * khp[dd];
        dot *= 0.125f;
        float m = dot;
#pragma unroll
        for (int o = 16; o > 0; o >>= 1) m = fmaxf(m, __shfl_xor_sync(0xffffffffu, m, o));
        float e = __expf(dot - m);
        float sum = e;
#pragma unroll
        for (int o = 16; o > 0; o >>= 1) sum += __shfl_xor_sync(0xffffffffu, sum, o);
        scS[h2 * 32 + t2] = e / sum;
    }
    __syncthreads();

    {
        float a = 0.f;
        const float* vb = g_xqn + (size_t)(b * 32) * NDIM + h * 64 + d;
#pragma unroll
        for (int tt = 0; tt < 32; tt++) a += scS[h * 32 + tt] * vb[tt * NDIM];
        float z = a + qhS[tid];
        zS[tid] = z;
        __syncthreads();
        if (tid < 16) {
            float s = 0.f, ssum = 0.f;
            for (int dd = 0; dd < 64; dd++) {
                float v = zS[tid * 64 + dd]; s += v; ssum += v * v;
            }
            float mu = s * (1.f / 64.f);
            float var = (ssum - 64.f * mu * mu) * (1.f / 63.f);
            muS[tid] = mu;
            isdS[tid] = 1.f / (sqrtf(fmaxf(var, 0.f)) + 1e-6f);
        }
        __syncthreads();
        q_S[tid] = n1a[(i * 16 + h) * 64 + d] * (zS[tid] - muS[h]) * isdS[h]
                 + n1b[(i * 16 + h) * 64 + d];
    }
    __syncthreads();

    if (tid < 512) {
        const float* w1 = fw1 + ((size_t)(i * 16 + h2) * 32 + t2) * 64;
        float acc = fb1[(i * 16 + h2) * 32 + t2];
#pragma unroll
        for (int dd = 0; dd < 64; dd++) acc += q_S[h2 * 64 + dd] * w1[dd];
        hidS[h2 * 32 + t2] = fmaxf(acc, 0.f);
    }
    __syncthreads();

    float qv;
    {
        const float* w2 = fw2 + ((size_t)(i * 16 + h) * 64 + d) * 32;
        float acc = fb2[(i * 16 + h) * 64 + d];
#pragma unroll
        for (int ff = 0; ff < 32; ff++) acc += hidS[h * 32 + ff] * w2[ff];
        float z = q_S[tid] + acc;
        __syncthreads();
        zS[tid] = z;
        __syncthreads();
        if (tid < 16) {
            float s = 0.f, ssum = 0.f;
            for (int dd = 0; dd < 64; dd++) {
                float v = zS[tid * 64 + dd]; s += v; ssum += v * v;
            }
            float mu = s * (1.f / 64.f);
            float var = (ssum - 64.f * mu * mu) * (1.f / 63.f);
            muS[tid] = mu;
            isdS[tid] = 1.f / (sqrtf(fmaxf(var, 0.f)) + 1e-6f);
        }
        __syncthreads();
        qv = n2a[(i * 16 + h) * 64 + d] * (zS[tid] - muS[h]) * isdS[h]
           + n2b[(i * 16 + h) * 64 + d];
    }

    if (!last) {
        g_q[b * 1024 + tid] = qv;
        return;
    }

    float ssq = qv * qv;
#pragma unroll
    for (int o = 16; o > 0; o >>= 1) ssq += __shfl_xor_sync(0xffffffffu, ssq, o);
    if ((tid & 31) == 0) redA[tid >> 5] = ssq;
    __syncthreads();
    if (tid < 32) {
        float s2 = redA[tid];
#pragma unroll
        for (int o = 16; o > 0; o >>= 1) s2 += __shfl_xor_sync(0xffffffffu, s2, o);
        if (tid == 0) redA[0] = s2;
    }
    __syncthreads();
    float nrm = sqrtf(redA[0]);
    out[b * 1024 + tid] = qv / fmaxf(nrm, 1e-12f);
}

// ================= launch =================
extern "C" void kernel_launch(void* const* d_in, const int* in_sizes, int n_in,
                              void* d_out, int out_size) {
    const float* x     = (const float*)d_in[0];
    const float* gamma = (const float*)d_in[1];
    const float* beta  = (const float*)d_in[2];
    const float* qpr   = (const float*)d_in[3];
    const float* qlw   = (const float*)d_in[4];
    const float* qlb   = (const float*)d_in[5];
    const float* n1a   = (const float*)d_in[6];
    const float* n1b   = (const float*)d_in[7];
    const float* n2a   = (const float*)d_in[8];
    const float* n2b   = (const float*)d_in[9];
    const float* fw1   = (const float*)d_in[10];
    const float* fb1   = (const float*)d_in[11];
    const float* fw2   = (const float*)d_in[12];
    const float* fb2   = (const float*)d_in[13];
    float* out = (float*)d_out;

    prep_scales<<<256, 256>>>(gamma, beta);
    prep_A<<<dim3(KDIM / 1024, MDIM), 256>>>(x);
    prep_W<<<(NDIM * KDIM / 1024), 256>>>(qpr);

    cudaFuncSetAttribute(gemm_k, cudaFuncAttributeMaxDynamicSharedMemorySize, SMEM_TOTAL);
    gemm_k<<<dim3(NDIM / BN, MDIM / BM, SPLITK), 256, SMEM_TOTAL>>>();

    reduce_ln<<<MDIM, 256>>>();

    float* g_xqn_p = nullptr;
    float* g_q_p = nullptr;
    cudaGetSymbolAddress((void**)&g_xqn_p, g_xqn);
    cudaGetSymbolAddress((void**)&g_q_p, g_q);

    for (int i = 0; i < 3; i++) {
        if (i == 0)
            gemv_k<<<dim3(16, 8), 256>>>(qlw, qlb, g_xqn_p, 32 * NDIM, 16 * NDIM, 0);
        else
            gemv_k<<<dim3(16, 8), 256>>>(qlw, qlb, g_q_p, NDIM, 0, i);
        rest_k<<<8, 1024>>>(n1a, n1b, n2a, n2b, fw1, fb1, fw2, fb2,
                            i, (i == 2) ? 1 : 0, out);
    }
}

// round 6
// speedup vs baseline: 3.2806x; 1.0531x over previous
#include <cuda_runtime.h>
#include <cuda_fp16.h>
#include <cstdint>
#include <math.h>

// ---------------- problem constants ----------------
#define KDIM 100352          // 2048*49
#define MDIM 256             // b*t
#define NDIM 1024            // D = H*d
#define NF   2048
#define TT   32
#define SQRT_NF 45.254833995939045f
#define INV_SQRT_BN 0.9999950000374997f   // 1/sqrt(1+1e-5)

// ---------------- GEMM tiling ----------------
#define BM 256               // full M: W read exactly once
#define BN 64
#define BK 64                // 64 fp16 = 128 bytes = one smem row
#define SPLITK 18
#define KTILES 1568          // KDIM/BK
#define CHUNK  88            // ceil(KTILES/SPLITK); last chunk = 72

// per stage: A 256 rows x 128B = 32KB, B 64 rows x 128B = 8KB
#define A_BYTES 32768
#define STAGE_B 40960
#define SMEM_TOTAL (2 * STAGE_B)   // 81920

// ---------------- scratch (allocation-free: device globals) ----------------
__device__ __half g_Ah[(size_t)MDIM * KDIM];
__device__ float g_part[(size_t)SPLITK * MDIM * NDIM]; // split-K partials
__device__ float g_xqn[MDIM * NDIM];                   // layernormed xq
__device__ float g_off[TT * NF];                       // beta*sqrtNF + pe[t][c]
__device__ float g_sc[NF];                             // per-channel scale
__device__ float g_q[8 * NDIM];                        // evolving q
__device__ float g_qh[8 * NDIM];                       // relu(q @ W^T + b)

// ================= prep: scales + positional encoding =================
__global__ void prep_scales(const float* __restrict__ gamma,
                            const float* __restrict__ beta) {
    int idx = blockIdx.x * 256 + threadIdx.x;      // 65536 = 32*2048
    int t = idx >> 11;
    int c = idx & (NF - 1);
    float w = __expf(-(2.0f * (float)c / (float)NF) * 9.210340371976184f); // ln(10000)
    float ang = (float)t * w;
    float pe = (c & 1) ? cosf(ang) : sinf(ang);
    g_off[idx] = beta[c] * SQRT_NF + pe;
    if (idx < NF) g_sc[idx] = gamma[idx] * SQRT_NF * INV_SQRT_BN;
}

// ========== prep A: affine -> fp16 (4 elems/thread) ==========
__global__ void prep_A(const float* __restrict__ x) {
    int n = blockIdx.y;
    int k = (blockIdx.x * 256 + threadIdx.x) * 4;   // gridDim.x = KDIM/1024 = 98
    size_t id = (size_t)n * KDIM + k;
    float4 xv = *(const float4*)(x + id);
    int to = (n & 31) * NF;
    __half2 hv[2];
    hv[0] = __floats2half2_rn(xv.x * g_sc[k / 49]       + g_off[to + k / 49],
                              xv.y * g_sc[(k + 1) / 49] + g_off[to + (k + 1) / 49]);
    hv[1] = __floats2half2_rn(xv.z * g_sc[(k + 2) / 49] + g_off[to + (k + 2) / 49],
                              xv.w * g_sc[(k + 3) / 49] + g_off[to + (k + 3) / 49]);
    *(uint2*)(g_Ah + id) = *(uint2*)hv;
}

// ================= fp16 GEMM, W converted in-loader =================
__device__ __forceinline__ void mma16(float* c, const uint32_t* a, const uint32_t* b) {
    asm volatile(
        "mma.sync.aligned.m16n8k16.row.col.f32.f16.f16.f32 "
        "{%0,%1,%2,%3},{%4,%5,%6,%7},{%8,%9},{%0,%1,%2,%3};"
        : "+f"(c[0]), "+f"(c[1]), "+f"(c[2]), "+f"(c[3])
        : "r"(a[0]), "r"(a[1]), "r"(a[2]), "r"(a[3]), "r"(b[0]), "r"(b[1]));
}
__device__ __forceinline__ uint32_t lds32(uint32_t a) {
    uint32_t v;
    asm volatile("ld.shared.b32 %0, [%1];" : "=r"(v) : "r"(a));
    return v;
}

__global__ void __launch_bounds__(256, 2) gemm_k(const float* __restrict__ Wt) {
    extern __shared__ char smem[];
    const uint32_t sbase = (uint32_t)__cvta_generic_to_shared(smem);
    const int tid = threadIdx.x;
    const int lane = tid & 31, wid = tid >> 5;
    const int g = lane >> 2, tg = lane & 3;
    const int wm = wid >> 1, wn = wid & 1;          // 4x2 warps, tile 64x32
    const int nt = blockIdx.x, ks = blockIdx.z;
    const int k0t = ks * CHUNK;
    int nkt = KTILES - k0t; if (nkt > CHUNK) nkt = CHUNK;
    const int k0 = k0t * BK;

    // ---- loader geometry ----
    const int r0 = tid >> 3;             // 0..31
    const int part = tid & 7;            // 16B chunk within 128B row
    const uint32_t swz = (uint32_t)((part * 16) ^ ((r0 & 7) << 4));

    // A: 8 chunks/thread, rows r0 + 32j (j=0..7), fp16 source via cp.async
    const __half* pA0 = g_Ah + (size_t)r0 * KDIM + k0 + part * 8;
    const uint32_t dA0 = (uint32_t)r0 * 128u + swz;
    // B: 2 chunks/thread, rows r0 + 32j (j=0..1), fp32 source -> cvt -> STS
    const float* pB0 = Wt + ((size_t)(nt * BN) + r0) * KDIM + k0 + part * 8;
    const uint32_t dB0 = (uint32_t)A_BYTES + (uint32_t)r0 * 128u + swz;

    auto ldA = [&](int s, int kt) {
        uint32_t sb = sbase + (uint32_t)s * STAGE_B;
        const __half* p = pA0 + (size_t)kt * BK;
#pragma unroll
        for (int j = 0; j < 8; j++) {
            asm volatile("cp.async.cg.shared.global [%0], [%1], 16;"
                         :: "r"(sb + dA0 + j * 4096u), "l"(p + (size_t)j * 32 * KDIM));
        }
        asm volatile("cp.async.commit_group;" ::: "memory");
    };

    float4 rb[2][2][2];                 // [chunk j][which float4] x 2 bufs folded below
    auto ldB = [&](float4 r[2][2], int kt) {
#pragma unroll
        for (int j = 0; j < 2; j++) {
            const float4* p = (const float4*)(pB0 + (size_t)j * 32 * KDIM + (size_t)kt * BK);
            r[j][0] = p[0];
            r[j][1] = p[1];
        }
    };
    auto stB = [&](int s, float4 r[2][2]) {
        uint32_t sb = sbase + (uint32_t)s * STAGE_B;
#pragma unroll
        for (int j = 0; j < 2; j++) {
            __half2 h[4];
            h[0] = __floats2half2_rn(r[j][0].x, r[j][0].y);
            h[1] = __floats2half2_rn(r[j][0].z, r[j][0].w);
            h[2] = __floats2half2_rn(r[j][1].x, r[j][1].y);
            h[3] = __floats2half2_rn(r[j][1].z, r[j][1].w);
            asm volatile("st.shared.v4.b32 [%0], {%1,%2,%3,%4};"
                         :: "r"(sb + dB0 + j * 4096u),
                            "r"(*(uint32_t*)&h[0]), "r"(*(uint32_t*)&h[1]),
                            "r"(*(uint32_t*)&h[2]), "r"(*(uint32_t*)&h[3]) : "memory");
        }
    };

    // fragment columns: byte = jj*16 + tg*4 logical, swizzled by row&7 == g
    uint32_t col[8];
#pragma unroll
    for (int jj = 0; jj < 8; jj++) col[jj] = (uint32_t)(((jj ^ g) << 4) + tg * 4);
    uint32_t rowA[4][2], rowB[4];
#pragma unroll
    for (int mi = 0; mi < 4; mi++) {
        rowA[mi][0] = (uint32_t)(wm * 64 + mi * 16 + g) * 128u;
        rowA[mi][1] = rowA[mi][0] + 8u * 128u;
    }
#pragma unroll
    for (int ni = 0; ni < 4; ni++)
        rowB[ni] = (uint32_t)A_BYTES + (uint32_t)(wn * 32 + ni * 8 + g) * 128u;

    float acc[4][4][4];
#pragma unroll
    for (int a = 0; a < 4; a++)
#pragma unroll
        for (int b = 0; b < 4; b++)
#pragma unroll
            for (int cc = 0; cc < 4; cc++) acc[a][b][cc] = 0.f;

    // ---- prologue: stages 0 and 1 ----
    ldB(rb[0], 0); ldA(0, 0); stB(0, rb[0]);
    ldB(rb[1], 1); ldA(1, 1); stB(1, rb[1]);

    for (int kt = 0; kt < nkt; kt++) {
        const int s = kt & 1;
        if (kt + 1 < nkt) { asm volatile("cp.async.wait_group 1;" ::: "memory"); }
        else              { asm volatile("cp.async.wait_group 0;" ::: "memory"); }
        __syncthreads();

        if (kt + 2 < nkt) ldB(rb[s], kt + 2);     // prefetch next-next B into regs

        uint32_t sb = sbase + (uint32_t)s * STAGE_B;
#pragma unroll
        for (int ks2 = 0; ks2 < 4; ks2++) {          // 4 x k16 per BK=64 row
            const int j0 = ks2 * 2;
            uint32_t ah[4][4];
#pragma unroll
            for (int mi = 0; mi < 4; mi++) {
                uint32_t r0a = sb + rowA[mi][0], r1a = sb + rowA[mi][1];
                ah[mi][0] = lds32(r0a + col[j0]);     ah[mi][1] = lds32(r1a + col[j0]);
                ah[mi][2] = lds32(r0a + col[j0 + 1]); ah[mi][3] = lds32(r1a + col[j0 + 1]);
            }
            uint32_t bh[4][2];
#pragma unroll
            for (int ni = 0; ni < 4; ni++) {
                uint32_t rbb = sb + rowB[ni];
                bh[ni][0] = lds32(rbb + col[j0]);     bh[ni][1] = lds32(rbb + col[j0 + 1]);
            }
#pragma unroll
            for (int mi = 0; mi < 4; mi++)
#pragma unroll
                for (int ni = 0; ni < 4; ni++)
                    mma16(acc[mi][ni], ah[mi], bh[ni]);
        }

        if (kt + 2 < nkt) {
            __syncthreads();                        // stage s fully consumed by all warps
            ldA(s, kt + 2);
            stB(s, rb[s]);
        }
    }

    // ---- epilogue: write split-K partials ----
    float* outp = g_part + (size_t)ks * MDIM * NDIM;
#pragma unroll
    for (int mi = 0; mi < 4; mi++) {
        int r = wm * 64 + mi * 16 + g;
#pragma unroll
        for (int ni = 0; ni < 4; ni++) {
            int c = nt * BN + wn * 32 + ni * 8 + 2 * tg;
            *(float2*)&outp[(size_t)r * NDIM + c] =
                make_float2(acc[mi][ni][0], acc[mi][ni][1]);
            *(float2*)&outp[(size_t)(r + 8) * NDIM + c] =
                make_float2(acc[mi][ni][2], acc[mi][ni][3]);
        }
    }
}

// ============ split-K reduce + ReLU + LayerNorm(ddof=1) over D ============
__global__ void reduce_ln() {
    int row = blockIdx.x, tid = threadIdx.x;
    float v[4], s = 0.f, ss = 0.f;
#pragma unroll
    for (int j = 0; j < 4; j++) {
        int col = tid + j * 256;
        float a = 0.f;
#pragma unroll
        for (int sk = 0; sk < SPLITK; sk++)
            a += g_part[((size_t)sk * MDIM + row) * NDIM + col];
        a = fmaxf(a, 0.f);
        v[j] = a; s += a; ss += a * a;
    }
    __shared__ float r1[8], r2[8];
#pragma unroll
    for (int o = 16; o > 0; o >>= 1) {
        s  += __shfl_xor_sync(0xffffffffu, s, o);
        ss += __shfl_xor_sync(0xffffffffu, ss, o);
    }
    if ((tid & 31) == 0) { r1[tid >> 5] = s; r2[tid >> 5] = ss; }
    __syncthreads();
    if (tid == 0) {
        float S = 0.f, SS = 0.f;
        for (int w = 0; w < 8; w++) { S += r1[w]; SS += r2[w]; }
        r1[0] = S; r2[0] = SS;
    }
    __syncthreads();
    float mean = r1[0] * (1.f / 1024.f);
    float var  = (r2[0] - 1024.f * mean * mean) * (1.f / 1023.f);
    float inv  = 1.f / (sqrtf(fmaxf(var, 0.f)) + 1e-6f);
#pragma unroll
    for (int j = 0; j < 4; j++)
        g_xqn[row * NDIM + tid + j * 256] = (v[j] - mean) * inv;
}

// ============ qh = relu(q @ qlin_w[i].T + qlin_b[i]), 128 blocks ============
__global__ void __launch_bounds__(256) gemv_k(
    const float* __restrict__ qlw, const float* __restrict__ qlb,
    const float* __restrict__ qsrc, int qrowstride, int qoff, int i)
{
    const int b = blockIdx.y, c = blockIdx.x;     // grid (16, 8)
    const int tid = threadIdx.x;
    const int o = c * 64 + (tid >> 2);            // output index
    const int part = tid & 3;

    __shared__ float qS[1024];
    const float* qp = qsrc + (size_t)b * qrowstride + qoff;
#pragma unroll
    for (int j = tid; j < 1024; j += 256) qS[j] = qp[j];
    __syncthreads();

    const float4* W4 = (const float4*)(qlw + ((size_t)i * 1024 + o) * 1024 + part * 256);
    const float* qb = qS + part * 256;
    float acc = 0.f;
#pragma unroll 8
    for (int j = 0; j < 64; j++) {
        float4 w = W4[j];
        acc += w.x * qb[j * 4] + w.y * qb[j * 4 + 1]
             + w.z * qb[j * 4 + 2] + w.w * qb[j * 4 + 3];
    }
    acc += __shfl_xor_sync(0xffffffffu, acc, 1);
    acc += __shfl_xor_sync(0xffffffffu, acc, 2);
    if (part == 0) g_qh[b * 1024 + o] = fmaxf(acc + qlb[i * 1024 + o], 0.f);
}

// ============ attention rest: softmax + AV + norms + FFN ============
__global__ void __launch_bounds__(1024) rest_k(
    const float* __restrict__ n1a, const float* __restrict__ n1b,
    const float* __restrict__ n2a, const float* __restrict__ n2b,
    const float* __restrict__ fw1, const float* __restrict__ fb1,
    const float* __restrict__ fw2, const float* __restrict__ fb2,
    int i, int last, float* __restrict__ out)
{
    const int b = blockIdx.x, tid = threadIdx.x;
    const int h = tid >> 6, d = tid & 63;     // 16 x 64
    const int h2 = tid >> 5, t2 = tid & 31;   // 16 x 32 (tid < 512)

    __shared__ float qhS[1024], q_S[1024], zS[1024];
    __shared__ float scS[16 * 32], hidS[16 * 32];
    __shared__ float muS[16], isdS[16], redA[32];

    qhS[tid] = g_qh[b * 1024 + tid];
    __syncthreads();

    if (tid < 512) {
        const float* khp = g_xqn + (b * 32 + t2) * NDIM + h2 * 64;
        const float* qp  = qhS + h2 * 64;
        float dot = 0.f;
#pragma unroll
        for (int dd = 0; dd < 64; dd++) dot += qp[dd] * khp[dd];
        dot *= 0.125f;
        float m = dot;
#pragma unroll
        for (int o = 16; o > 0; o >>= 1) m = fmaxf(m, __shfl_xor_sync(0xffffffffu, m, o));
        float e = __expf(dot - m);
        float sum = e;
#pragma unroll
        for (int o = 16; o > 0; o >>= 1) sum += __shfl_xor_sync(0xffffffffu, sum, o);
        scS[h2 * 32 + t2] = e / sum;
    }
    __syncthreads();

    {
        float a = 0.f;
        const float* vb = g_xqn + (size_t)(b * 32) * NDIM + h * 64 + d;
#pragma unroll
        for (int tt = 0; tt < 32; tt++) a += scS[h * 32 + tt] * vb[tt * NDIM];
        float z = a + qhS[tid];
        zS[tid] = z;
        __syncthreads();
        if (tid < 16) {
            float s = 0.f, ssum = 0.f;
            for (int dd = 0; dd < 64; dd++) {
                float v = zS[tid * 64 + dd]; s += v; ssum += v * v;
            }
            float mu = s * (1.f / 64.f);
            float var = (ssum - 64.f * mu * mu) * (1.f / 63.f);
            muS[tid] = mu;
            isdS[tid] = 1.f / (sqrtf(fmaxf(var, 0.f)) + 1e-6f);
        }
        __syncthreads();
        q_S[tid] = n1a[(i * 16 + h) * 64 + d] * (zS[tid] - muS[h]) * isdS[h]
                 + n1b[(i * 16 + h) * 64 + d];
    }
    __syncthreads();

    if (tid < 512) {
        const float* w1 = fw1 + ((size_t)(i * 16 + h2) * 32 + t2) * 64;
        float acc = fb1[(i * 16 + h2) * 32 + t2];
#pragma unroll
        for (int dd = 0; dd < 64; dd++) acc += q_S[h2 * 64 + dd] * w1[dd];
        hidS[h2 * 32 + t2] = fmaxf(acc, 0.f);
    }
    __syncthreads();

    float qv;
    {
        const float* w2 = fw2 + ((size_t)(i * 16 + h) * 64 + d) * 32;
        float acc = fb2[(i * 16 + h) * 64 + d];
#pragma unroll
        for (int ff = 0; ff < 32; ff++) acc += hidS[h * 32 + ff] * w2[ff];
        float z = q_S[tid] + acc;
        __syncthreads();
        zS[tid] = z;
        __syncthreads();
        if (tid < 16) {
            float s = 0.f, ssum = 0.f;
            for (int dd = 0; dd < 64; dd++) {
                float v = zS[tid * 64 + dd]; s += v; ssum += v * v;
            }
            float mu = s * (1.f / 64.f);
            float var = (ssum - 64.f * mu * mu) * (1.f / 63.f);
            muS[tid] = mu;
            isdS[tid] = 1.f / (sqrtf(fmaxf(var, 0.f)) + 1e-6f);
        }
        __syncthreads();
        qv = n2a[(i * 16 + h) * 64 + d] * (zS[tid] - muS[h]) * isdS[h]
           + n2b[(i * 16 + h) * 64 + d];
    }

    if (!last) {
        g_q[b * 1024 + tid] = qv;
        return;
    }

    float ssq = qv * qv;
#pragma unroll
    for (int o = 16; o > 0; o >>= 1) ssq += __shfl_xor_sync(0xffffffffu, ssq, o);
    if ((tid & 31) == 0) redA[tid >> 5] = ssq;
    __syncthreads();
    if (tid < 32) {
        float s2 = redA[tid];
#pragma unroll
        for (int o = 16; o > 0; o >>= 1) s2 += __shfl_xor_sync(0xffffffffu, s2, o);
        if (tid == 0) redA[0] = s2;
    }
    __syncthreads();
    float nrm = sqrtf(redA[0]);
    out[b * 1024 + tid] = qv / fmaxf(nrm, 1e-12f);
}

// ================= launch =================
extern "C" void kernel_launch(void* const* d_in, const int* in_sizes, int n_in,
                              void* d_out, int out_size) {
    const float* x     = (const float*)d_in[0];
    const float* gamma = (const float*)d_in[1];
    const float* beta  = (const float*)d_in[2];
    const float* qpr   = (const float*)d_in[3];
    const float* qlw   = (const float*)d_in[4];
    const float* qlb   = (const float*)d_in[5];
    const float* n1a   = (const float*)d_in[6];
    const float* n1b   = (const float*)d_in[7];
    const float* n2a   = (const float*)d_in[8];
    const float* n2b   = (const float*)d_in[9];
    const float* fw1   = (const float*)d_in[10];
    const float* fb1   = (const float*)d_in[11];
    const float* fw2   = (const float*)d_in[12];
    const float* fb2   = (const float*)d_in[13];
    float* out = (float*)d_out;

    prep_scales<<<256, 256>>>(gamma, beta);
    prep_A<<<dim3(KDIM / 1024, MDIM), 256>>>(x);

    cudaFuncSetAttribute(gemm_k, cudaFuncAttributeMaxDynamicSharedMemorySize, SMEM_TOTAL);
    gemm_k<<<dim3(NDIM / BN, 1, SPLITK), 256, SMEM_TOTAL>>>(qpr);

    reduce_ln<<<MDIM, 256>>>();

    float* g_xqn_p = nullptr;
    float* g_q_p = nullptr;
    cudaGetSymbolAddress((void**)&g_xqn_p, g_xqn);
    cudaGetSymbolAddress((void**)&g_q_p, g_q);

    for (int i = 0; i < 3; i++) {
        if (i == 0)
            gemv_k<<<dim3(16, 8), 256>>>(qlw, qlb, g_xqn_p, 32 * NDIM, 16 * NDIM, 0);
        else
            gemv_k<<<dim3(16, 8), 256>>>(qlw, qlb, g_q_p, NDIM, 0, i);
        rest_k<<<8, 1024>>>(n1a, n1b, n2a, n2b, fw1, fb1, fw2, fb2,
                            i, (i == 2) ? 1 : 0, out);
    }
}

// round 8
// speedup vs baseline: 3.6537x; 1.1137x over previous
#include <cuda_runtime.h>
#include <cuda_fp16.h>
#include <cstdint>
#include <math.h>

// ---------------- problem constants ----------------
#define KDIM 100352          // 2048*49
#define MDIM 256             // b*t
#define NDIM 1024            // D = H*d
#define NF   2048
#define TT   32
#define SQRT_NF 45.254833995939045f
#define INV_SQRT_BN 0.9999950000374997f   // 1/sqrt(1+1e-5)

// ---------------- GEMM tiling ----------------
#define BM 256               // full M: W read exactly once
#define BN 64
#define BK 64
#define SPLITK 18
#define KTILES 1568          // KDIM/BK
#define CHUNK  88            // ceil(KTILES/SPLITK); last chunk = 72

// per stage: A 256 rows x 128B fp16 = 32KB ; B 64 rows x 256B fp32 = 16KB
#define A_BYTES 32768
#define STAGE_B 49152
#define SMEM_TOTAL (2 * STAGE_B)   // 98304

// ---------------- scratch (allocation-free: device globals) ----------------
__device__ __half g_Ah[(size_t)MDIM * KDIM];
__device__ float g_part[(size_t)SPLITK * MDIM * NDIM]; // split-K partials
__device__ float g_xqn[MDIM * NDIM];                   // layernormed xq
__device__ float g_off[TT * NF];                       // beta*sqrtNF + pe[t][c]
__device__ float g_sc[NF];                             // per-channel scale
__device__ float g_q[8 * NDIM];                        // evolving q
__device__ float g_qh[8 * NDIM];                       // relu(q @ W^T + b)

// ================= prep: scales + positional encoding =================
__global__ void prep_scales(const float* __restrict__ gamma,
                            const float* __restrict__ beta) {
    int idx = blockIdx.x * 256 + threadIdx.x;      // 65536 = 32*2048
    int t = idx >> 11;
    int c = idx & (NF - 1);
    float w = __expf(-(2.0f * (float)c / (float)NF) * 9.210340371976184f); // ln(10000)
    float ang = (float)t * w;
    float pe = (c & 1) ? cosf(ang) : sinf(ang);
    g_off[idx] = beta[c] * SQRT_NF + pe;
    if (idx < NF) g_sc[idx] = gamma[idx] * SQRT_NF * INV_SQRT_BN;
}

// ========== prep A: affine -> fp16 (4 elems/thread) ==========
__global__ void prep_A(const float* __restrict__ x) {
    int n = blockIdx.y;
    int k = (blockIdx.x * 256 + threadIdx.x) * 4;   // gridDim.x = KDIM/1024 = 98
    size_t id = (size_t)n * KDIM + k;
    float4 xv = *(const float4*)(x + id);
    int to = (n & 31) * NF;
    __half2 hv[2];
    hv[0] = __floats2half2_rn(xv.x * g_sc[k / 49]       + g_off[to + k / 49],
                              xv.y * g_sc[(k + 1) / 49] + g_off[to + (k + 1) / 49]);
    hv[1] = __floats2half2_rn(xv.z * g_sc[(k + 2) / 49] + g_off[to + (k + 2) / 49],
                              xv.w * g_sc[(k + 3) / 49] + g_off[to + (k + 3) / 49]);
    *(uint2*)(g_Ah + id) = *(uint2*)hv;
}

// ================= fp16 GEMM, W kept fp32 in smem, cvt at fragment time =====
__device__ __forceinline__ void mma16(float* c, const uint32_t* a, const uint32_t* b) {
    asm volatile(
        "mma.sync.aligned.m16n8k16.row.col.f32.f16.f16.f32 "
        "{%0,%1,%2,%3},{%4,%5,%6,%7},{%8,%9},{%0,%1,%2,%3};"
        : "+f"(c[0]), "+f"(c[1]), "+f"(c[2]), "+f"(c[3])
        : "r"(a[0]), "r"(a[1]), "r"(a[2]), "r"(a[3]), "r"(b[0]), "r"(b[1]));
}
__device__ __forceinline__ uint32_t lds32(uint32_t a) {
    uint32_t v;
    asm volatile("ld.shared.b32 %0, [%1];" : "=r"(v) : "r"(a));
    return v;
}
__device__ __forceinline__ float2 lds64(uint32_t a) {
    float2 v;
    asm volatile("ld.shared.v2.f32 {%0,%1}, [%2];" : "=f"(v.x), "=f"(v.y) : "r"(a));
    return v;
}
__device__ __forceinline__ uint32_t packh2(float hi, float lo) {
    uint32_t d;
    asm("cvt.rn.f16x2.f32 %0, %1, %2;" : "=r"(d) : "f"(hi), "f"(lo));
    return d;
}

__global__ void __launch_bounds__(256, 2) gemm_k(const float* __restrict__ Wt) {
    extern __shared__ char smem[];
    const uint32_t sbase = (uint32_t)__cvta_generic_to_shared(smem);
    const int tid = threadIdx.x;
    const int lane = tid & 31, wid = tid >> 5;
    const int g = lane >> 2, tg = lane & 3;
    const int wm = wid >> 1, wn = wid & 1;          // 4x2 warps, tile 64x32
    const int nt = blockIdx.x, ks = blockIdx.z;
    const int k0t = ks * CHUNK;
    int nkt = KTILES - k0t; if (nkt > CHUNK) nkt = CHUNK;
    const int k0 = k0t * BK;

    // ---- A loader: 8 x 16B chunks/thread (fp16, 128B rows, 16B-granule swizzle)
    const int rA = tid >> 3, pa = tid & 7;
    const uint32_t dA0 = (uint32_t)rA * 128u + (uint32_t)((pa * 16) ^ ((rA & 7) << 4));
    const __half* pA0 = g_Ah + (size_t)rA * KDIM + k0 + pa * 8;

    // ---- B loader: 4 x 16B chunks/thread (fp32, 256B rows, 32B-granule swizzle)
    const int rB = tid >> 2, chB = tid & 3;
    uint32_t dB[4];
#pragma unroll
    for (int u = 0; u < 4; u++)
        dB[u] = (uint32_t)A_BYTES + (uint32_t)rB * 256u
              + (uint32_t)((chB * 16 + 64 * u) ^ ((rB & 7) << 5));
    const float* pB0 = Wt + ((size_t)(nt * BN) + rB) * KDIM + k0 + chB * 4;

    auto ldAB = [&](int s, int kt) {
        uint32_t sb = sbase + (uint32_t)s * STAGE_B;
        const __half* ap = pA0 + (size_t)kt * BK;
#pragma unroll
        for (int j = 0; j < 8; j++)
            asm volatile("cp.async.cg.shared.global [%0], [%1], 16;"
                         :: "r"(sb + dA0 + j * 4096u), "l"(ap + (size_t)j * 32 * KDIM));
        const float* bp = pB0 + (size_t)kt * BK;
#pragma unroll
        for (int u = 0; u < 4; u++)
            asm volatile("cp.async.cg.shared.global [%0], [%1], 16;"
                         :: "r"(sb + dB[u]), "l"(bp + u * 16));
        asm volatile("cp.async.commit_group;" ::: "memory");
    };

    // ---- fragment addressing ----
    uint32_t col[8];
#pragma unroll
    for (int jj = 0; jj < 8; jj++) col[jj] = (uint32_t)(((jj ^ g) << 4) + tg * 4);
    uint32_t rowA[4][2], rowB[4];
#pragma unroll
    for (int mi = 0; mi < 4; mi++) {
        rowA[mi][0] = (uint32_t)(wm * 64 + mi * 16 + g) * 128u;
        rowA[mi][1] = rowA[mi][0] + 8u * 128u;
    }
#pragma unroll
    for (int ni = 0; ni < 4; ni++)
        rowB[ni] = (uint32_t)A_BYTES + (uint32_t)(wn * 32 + ni * 8 + g) * 256u;
    const uint32_t gkey = (uint32_t)(g << 5);       // B swizzle key (row&7 == g)

    float acc[4][4][4];
#pragma unroll
    for (int a = 0; a < 4; a++)
#pragma unroll
        for (int b = 0; b < 4; b++)
#pragma unroll
            for (int cc = 0; cc < 4; cc++) acc[a][b][cc] = 0.f;

    // ---- 2-stage pipeline ----
    ldAB(0, 0);
    ldAB(1, 1);

    for (int kt = 0; kt < nkt; kt++) {
        const int s = kt & 1;
        if (kt + 1 < nkt) { asm volatile("cp.async.wait_group 1;" ::: "memory"); }
        else              { asm volatile("cp.async.wait_group 0;" ::: "memory"); }
        __syncthreads();

        uint32_t sb = sbase + (uint32_t)s * STAGE_B;
#pragma unroll
        for (int ks2 = 0; ks2 < 4; ks2++) {          // 4 x k16 per BK=64
            const int j0 = ks2 * 2;
            uint32_t ah[4][4];
#pragma unroll
            for (int mi = 0; mi < 4; mi++) {
                uint32_t r0a = sb + rowA[mi][0], r1a = sb + rowA[mi][1];
                ah[mi][0] = lds32(r0a + col[j0]);     ah[mi][1] = lds32(r1a + col[j0]);
                ah[mi][2] = lds32(r0a + col[j0 + 1]); ah[mi][3] = lds32(r1a + col[j0 + 1]);
            }
            // logical within-row byte = 64*ks2 + 8*tg (+32 for k+8), swizzle by g<<5
            const uint32_t off0 = (uint32_t)(64 * ks2 + 8 * tg) ^ gkey;
            const uint32_t off1 = off0 ^ 32u;
            uint32_t bh[4][2];
#pragma unroll
            for (int ni = 0; ni < 4; ni++) {
                uint32_t rbb = sb + rowB[ni];
                float2 v0 = lds64(rbb + off0);
                float2 v1 = lds64(rbb + off1);
                bh[ni][0] = packh2(v0.y, v0.x);
                bh[ni][1] = packh2(v1.y, v1.x);
            }
#pragma unroll
            for (int mi = 0; mi < 4; mi++)
#pragma unroll
                for (int ni = 0; ni < 4; ni++)
                    mma16(acc[mi][ni], ah[mi], bh[ni]);
        }

        if (kt + 2 < nkt) {
            __syncthreads();                 // stage s consumed by all warps
            ldAB(s, kt + 2);
        }
    }

    // ---- epilogue: write split-K partials ----
    float* outp = g_part + (size_t)ks * MDIM * NDIM;
#pragma unroll
    for (int mi = 0; mi < 4; mi++) {
        int r = wm * 64 + mi * 16 + g;
#pragma unroll
        for (int ni = 0; ni < 4; ni++) {
            int c = nt * BN + wn * 32 + ni * 8 + 2 * tg;
            *(float2*)&outp[(size_t)r * NDIM + c] =
                make_float2(acc[mi][ni][0], acc[mi][ni][1]);
            *(float2*)&outp[(size_t)(r + 8) * NDIM + c] =
                make_float2(acc[mi][ni][2], acc[mi][ni][3]);
        }
    }
}

// ============ split-K reduce + ReLU + LayerNorm(ddof=1) over D ============
__global__ void reduce_ln() {
    int row = blockIdx.x, tid = threadIdx.x;
    float v[4], s = 0.f, ss = 0.f;
#pragma unroll
    for (int j = 0; j < 4; j++) {
        int col = tid + j * 256;
        float a = 0.f;
#pragma unroll
        for (int sk = 0; sk < SPLITK; sk++)
            a += g_part[((size_t)sk * MDIM + row) * NDIM + col];
        a = fmaxf(a, 0.f);
        v[j] = a; s += a; ss += a * a;
    }
    __shared__ float r1[8], r2[8];
#pragma unroll
    for (int o = 16; o > 0; o >>= 1) {
        s  += __shfl_xor_sync(0xffffffffu, s, o);
        ss += __shfl_xor_sync(0xffffffffu, ss, o);
    }
    if ((tid & 31) == 0) { r1[tid >> 5] = s; r2[tid >> 5] = ss; }
    __syncthreads();
    if (tid == 0) {
        float S = 0.f, SS = 0.f;
        for (int w = 0; w < 8; w++) { S += r1[w]; SS += r2[w]; }
        r1[0] = S; r2[0] = SS;
    }
    __syncthreads();
    float mean = r1[0] * (1.f / 1024.f);
    float var  = (r2[0] - 1024.f * mean * mean) * (1.f / 1023.f);
    float inv  = 1.f / (sqrtf(fmaxf(var, 0.f)) + 1e-6f);
#pragma unroll
    for (int j = 0; j < 4; j++)
        g_xqn[row * NDIM + tid + j * 256] = (v[j] - mean) * inv;
}

// ============ qh = relu(q @ qlin_w[i].T + qlin_b[i]), 128 blocks ============
__global__ void __launch_bounds__(256) gemv_k(
    const float* __restrict__ qlw, const float* __restrict__ qlb,
    const float* __restrict__ qsrc, int qrowstride, int qoff, int i)
{
    const int b = blockIdx.y, c = blockIdx.x;     // grid (16, 8)
    const int tid = threadIdx.x;
    const int o = c * 64 + (tid >> 2);            // output index
    const int part = tid & 3;

    __shared__ float qS[1024];
    const float* qp = qsrc + (size_t)b * qrowstride + qoff;
#pragma unroll
    for (int j = tid; j < 1024; j += 256) qS[j] = qp[j];
    __syncthreads();

    const float4* W4 = (const float4*)(qlw + ((size_t)i * 1024 + o) * 1024 + part * 256);
    const float* qb = qS + part * 256;
    float acc = 0.f;
#pragma unroll 8
    for (int j = 0; j < 64; j++) {
        float4 w = W4[j];
        acc += w.x * qb[j * 4] + w.y * qb[j * 4 + 1]
             + w.z * qb[j * 4 + 2] + w.w * qb[j * 4 + 3];
    }
    acc += __shfl_xor_sync(0xffffffffu, acc, 1);
    acc += __shfl_xor_sync(0xffffffffu, acc, 2);
    if (part == 0) g_qh[b * 1024 + o] = fmaxf(acc + qlb[i * 1024 + o], 0.f);
}

// ============ attention rest: softmax + AV + norms + FFN ============
__global__ void __launch_bounds__(1024) rest_k(
    const float* __restrict__ n1a, const float* __restrict__ n1b,
    const float* __restrict__ n2a, const float* __restrict__ n2b,
    const float* __restrict__ fw1, const float* __restrict__ fb1,
    const float* __restrict__ fw2, const float* __restrict__ fb2,
    int i, int last, float* __restrict__ out)
{
    const int b = blockIdx.x, tid = threadIdx.x;
    const int h = tid >> 6, d = tid & 63;     // 16 x 64
    const int h2 = tid >> 5, t2 = tid & 31;   // 16 x 32 (tid < 512)

    __shared__ float qhS[1024], q_S[1024], zS[1024];
    __shared__ float scS[16 * 32], hidS[16 * 32];
    __shared__ float muS[16], isdS[16], redA[32];

    qhS[tid] = g_qh[b * 1024 + tid];
    __syncthreads();

    if (tid < 512) {
        const float* khp = g_xqn + (b * 32 + t2) * NDIM + h2 * 64;
        const float* qp  = qhS + h2 * 64;
        float dot = 0.f;
#pragma unroll
        for (int dd = 0; dd < 64; dd++) dot += qp[dd] * khp[dd];
        dot *= 0.125f;
        float m = dot;
#pragma unroll
        for (int o = 16; o > 0; o >>= 1) m = fmaxf(m, __shfl_xor_sync(0xffffffffu, m, o));
        float e = __expf(dot - m);
        float sum = e;
#pragma unroll
        for (int o = 16; o > 0; o >>= 1) sum += __shfl_xor_sync(0xffffffffu, sum, o);
        scS[h2 * 32 + t2] = e / sum;
    }
    __syncthreads();

    {
        float a = 0.f;
        const float* vb = g_xqn + (size_t)(b * 32) * NDIM + h * 64 + d;
#pragma unroll
        for (int tt = 0; tt < 32; tt++) a += scS[h * 32 + tt] * vb[tt * NDIM];
        float z = a + qhS[tid];
        zS[tid] = z;
        __syncthreads();
        if (tid < 16) {
            float s = 0.f, ssum = 0.f;
            for (int dd = 0; dd < 64; dd++) {
                float v = zS[tid * 64 + dd]; s += v; ssum += v * v;
            }
            float mu = s * (1.f / 64.f);
            float var = (ssum - 64.f * mu * mu) * (1.f / 63.f);
            muS[tid] = mu;
            isdS[tid] = 1.f / (sqrtf(fmaxf(var, 0.f)) + 1e-6f);
        }
        __syncthreads();
        q_S[tid] = n1a[(i * 16 + h) * 64 + d] * (zS[tid] - muS[h]) * isdS[h]
                 + n1b[(i * 16 + h) * 64 + d];
    }
    __syncthreads();

    if (tid < 512) {
        const float* w1 = fw1 + ((size_t)(i * 16 + h2) * 32 + t2) * 64;
        float acc = fb1[(i * 16 + h2) * 32 + t2];
#pragma unroll
        for (int dd = 0; dd < 64; dd++) acc += q_S[h2 * 64 + dd] * w1[dd];
        hidS[h2 * 32 + t2] = fmaxf(acc, 0.f);
    }
    __syncthreads();

    float qv;
    {
        const float* w2 = fw2 + ((size_t)(i * 16 + h) * 64 + d) * 32;
        float acc = fb2[(i * 16 + h) * 64 + d];
#pragma unroll
        for (int ff = 0; ff < 32; ff++) acc += hidS[h * 32 + ff] * w2[ff];
        float z = q_S[tid] + acc;
        __syncthreads();
        zS[tid] = z;
        __syncthreads();
        if (tid < 16) {
            float s = 0.f, ssum = 0.f;
            for (int dd = 0; dd < 64; dd++) {
                float v = zS[tid * 64 + dd]; s += v; ssum += v * v;
            }
            float mu = s * (1.f / 64.f);
            float var = (ssum - 64.f * mu * mu) * (1.f / 63.f);
            muS[tid] = mu;
            isdS[tid] = 1.f / (sqrtf(fmaxf(var, 0.f)) + 1e-6f);
        }
        __syncthreads();
        qv = n2a[(i * 16 + h) * 64 + d] * (zS[tid] - muS[h]) * isdS[h]
           + n2b[(i * 16 + h) * 64 + d];
    }

    if (!last) {
        g_q[b * 1024 + tid] = qv;
        return;
    }

    float ssq = qv * qv;
#pragma unroll
    for (int o = 16; o > 0; o >>= 1) ssq += __shfl_xor_sync(0xffffffffu, ssq, o);
    if ((tid & 31) == 0) redA[tid >> 5] = ssq;
    __syncthreads();
    if (tid < 32) {
        float s2 = redA[tid];
#pragma unroll
        for (int o = 16; o > 0; o >>= 1) s2 += __shfl_xor_sync(0xffffffffu, s2, o);
        if (tid == 0) redA[0] = s2;
    }
    __syncthreads();
    float nrm = sqrtf(redA[0]);
    out[b * 1024 + tid] = qv / fmaxf(nrm, 1e-12f);
}

// ================= launch =================
extern "C" void kernel_launch(void* const* d_in, const int* in_sizes, int n_in,
                              void* d_out, int out_size) {
    const float* x     = (const float*)d_in[0];
    const float* gamma = (const float*)d_in[1];
    const float* beta  = (const float*)d_in[2];
    const float* qpr   = (const float*)d_in[3];
    const float* qlw   = (const float*)d_in[4];
    const float* qlb   = (const float*)d_in[5];
    const float* n1a   = (const float*)d_in[6];
    const float* n1b   = (const float*)d_in[7];
    const float* n2a   = (const float*)d_in[8];
    const float* n2b   = (const float*)d_in[9];
    const float* fw1   = (const float*)d_in[10];
    const float* fb1   = (const float*)d_in[11];
    const float* fw2   = (const float*)d_in[12];
    const float* fb2   = (const float*)d_in[13];
    float* out = (float*)d_out;

    prep_scales<<<256, 256>>>(gamma, beta);
    prep_A<<<dim3(KDIM / 1024, MDIM), 256>>>(x);

    cudaFuncSetAttribute(gemm_k, cudaFuncAttributeMaxDynamicSharedMemorySize, SMEM_TOTAL);
    gemm_k<<<dim3(NDIM / BN, 1, SPLITK), 256, SMEM_TOTAL>>>(qpr);

    reduce_ln<<<MDIM, 256>>>();

    float* g_xqn_p = nullptr;
    float* g_q_p = nullptr;
    cudaGetSymbolAddress((void**)&g_xqn_p, g_xqn);
    cudaGetSymbolAddress((void**)&g_q_p, g_q);

    for (int i = 0; i < 3; i++) {
        if (i == 0)
            gemv_k<<<dim3(16, 8), 256>>>(qlw, qlb, g_xqn_p, 32 * NDIM, 16 * NDIM, 0);
        else
            gemv_k<<<dim3(16, 8), 256>>>(qlw, qlb, g_q_p, NDIM, 0, i);
        rest_k<<<8, 1024>>>(n1a, n1b, n2a, n2b, fw1, fb1, fw2, fb2,
                            i, (i == 2) ? 1 : 0, out);
    }
}